// round 6
// baseline (speedup 1.0000x reference)
#include <cuda_runtime.h>
#include <math.h>

#define Lx   2
#define Bx   2
#define Sx   1024
#define Hx   768
#define NHx  12
#define HDx  64
#define Ex   8
#define KKx  2
#define Fx   3072
#define Vx   50257
#define Ntok (Bx*Sx)          /* 2048 */
#define NSLOT (Ntok*KKx)      /* 4096 */
#define EPSx 1e-5f

#define BM 128
#define BN 128
#define BKK 8

// ---------------- scratch (static __device__ arrays; allocation-free) -------
__device__ float g_x[Ntok*Hx];
__device__ float g_h[Ntok*Hx];
__device__ float g_q[Ntok*Hx];
__device__ float g_k[Ntok*Hx];
__device__ float g_v[Ntok*Hx];
__device__ float g_att[Ntok*Hx];
__device__ float g_scores[(size_t)Bx*NHx*Sx*Sx];   // ~100 MB
__device__ float g_act[(size_t)NSLOT*Fx];          // ~50 MB
__device__ float g_oe[(size_t)NSLOT*Hx];
__device__ float g_tp[NSLOT];
__device__ int   g_ti[NSLOT];
__device__ int   g_cnt[Ex];
__device__ int   g_off[Ex+1];
__device__ int   g_fill[Ex];
__device__ int   g_slot_tok[NSLOT];
__device__ int   g_tok2slot[NSLOT];

__device__ __forceinline__ float gelu_f(float x) {
    return 0.5f * x * (1.0f + erff(x * 0.70710678118654752440f));
}

// ---------------- embedding gather ------------------------------------------
__global__ void embed_k(const int* __restrict__ ids, const float* __restrict__ emb)
{
    int i = blockIdx.x * 256 + threadIdx.x;
    if (i >= Ntok*Hx) return;
    int n = i / Hx, hh = i % Hx;
    g_x[i] = emb[(size_t)ids[n]*Hx + hh];
}

// ---------------- layernorm (one block per token) ---------------------------
__global__ __launch_bounds__(256)
void ln_k(const float* __restrict__ X, const float* __restrict__ w,
          const float* __restrict__ b, float* __restrict__ Y)
{
    int n = blockIdx.x;
    __shared__ float sx[Hx];
    __shared__ float red[256];
    const float* xr = X + (size_t)n*Hx;
    int t = threadIdx.x;
    float s = 0.f;
    for (int i = t; i < Hx; i += 256) { float v = xr[i]; sx[i] = v; s += v; }
    red[t] = s; __syncthreads();
    for (int o = 128; o > 0; o >>= 1) { if (t < o) red[t] += red[t+o]; __syncthreads(); }
    float mean = red[0] * (1.0f/Hx);
    __syncthreads();
    float s2 = 0.f;
    for (int i = t; i < Hx; i += 256) { float d = sx[i]-mean; s2 += d*d; }
    __syncthreads();
    red[t] = s2; __syncthreads();
    for (int o = 128; o > 0; o >>= 1) { if (t < o) red[t] += red[t+o]; __syncthreads(); }
    float inv = rsqrtf(red[0] * (1.0f/Hx) + EPSx);
    for (int i = t; i < Hx; i += 256)
        Y[(size_t)n*Hx + i] = (sx[i]-mean)*inv*w[i] + b[i];
}

// ---------------- generic tiled SGEMM ---------------------------------------
// C[M,N] = act( alpha * A @ op(B) + bias ), optional C += (ADD)
// TB=0: B is [K,N] row-major (ldb); TB=1: B is [N,K] row-major (ldb).
// CSKIP=1: skip tiles fully above the causal diagonal (n0 > m0).
// KCLAMP=1: clamp the K loop to m0+BM (causal PV: attn cols > row are exact 0).
// Batched via blockIdx.z decomposed as (zb = z/zdiv, zh = z%zdiv) with strides.
template<int TB, int ACT, int ADD, int CSKIP = 0, int KCLAMP = 0>
__global__ __launch_bounds__(256)
void gemm_k(const float* __restrict__ A, const float* __restrict__ B,
            const float* __restrict__ bias, float* __restrict__ C,
            int M, int N, int Kd, int lda, int ldb, int ldc, float alpha,
            int zdiv, long long sAb, long long sAh, long long sBb, long long sBh,
            long long sCb, long long sCh)
{
    const int m0 = blockIdx.y * BM;
    const int n0 = blockIdx.x * BN;
    if (CSKIP && n0 > m0) return;          // fully-masked causal tile
    if (KCLAMP && m0 + BM < Kd) Kd = m0 + BM;  // remaining attn cols are exact 0
    if (zdiv > 0) {
        int z = blockIdx.z;
        int zb = z / zdiv, zh = z % zdiv;
        A += (long long)zb*sAb + (long long)zh*sAh;
        B += (long long)zb*sBb + (long long)zh*sBh;
        C += (long long)zb*sCb + (long long)zh*sCh;
    }
    __shared__ __align__(16) float As[BKK][BM];
    __shared__ __align__(16) float Bs[BKK][BN];
    const int tid = threadIdx.x;
    const int arow = tid >> 1, acol = (tid & 1) * 4;
    const int tr = (tid >> 4) << 3;
    const int tc = (tid & 15) << 3;

    float acc[8][8];
    #pragma unroll
    for (int i = 0; i < 8; i++)
        #pragma unroll
        for (int j = 0; j < 8; j++) acc[i][j] = 0.f;

    for (int k0 = 0; k0 < Kd; k0 += BKK) {
        { // A tile (Kd is always a multiple of 8; rows guarded)
            int gm = m0 + arow;
            float4 av = make_float4(0.f,0.f,0.f,0.f);
            if (gm < M) av = *(const float4*)&A[(size_t)gm*lda + k0 + acol];
            As[acol+0][arow] = av.x; As[acol+1][arow] = av.y;
            As[acol+2][arow] = av.z; As[acol+3][arow] = av.w;
        }
        if (TB) { // B[N,K]: load along K, transpose into Bs
            int bn = tid >> 1, bk = (tid & 1) * 4;
            int gn = n0 + bn;
            float4 bv = make_float4(0.f,0.f,0.f,0.f);
            if (gn < N) bv = *(const float4*)&B[(size_t)gn*ldb + k0 + bk];
            Bs[bk+0][bn] = bv.x; Bs[bk+1][bn] = bv.y;
            Bs[bk+2][bn] = bv.z; Bs[bk+3][bn] = bv.w;
        } else {  // B[K,N] (all NN uses have N % 4 == 0)
            int bk = tid >> 5, bn = (tid & 31) * 4;
            int gn = n0 + bn;
            float4 bv = make_float4(0.f,0.f,0.f,0.f);
            if (gn < N) bv = *(const float4*)&B[(size_t)(k0+bk)*ldb + gn];
            *(float4*)&Bs[bk][bn] = bv;
        }
        __syncthreads();
        #pragma unroll
        for (int kk = 0; kk < BKK; kk++) {
            float a[8], b[8];
            #pragma unroll
            for (int i = 0; i < 8; i++) a[i] = As[kk][tr+i];
            #pragma unroll
            for (int j = 0; j < 8; j++) b[j] = Bs[kk][tc+j];
            #pragma unroll
            for (int i = 0; i < 8; i++)
                #pragma unroll
                for (int j = 0; j < 8; j++)
                    acc[i][j] = fmaf(a[i], b[j], acc[i][j]);
        }
        __syncthreads();
    }
    #pragma unroll
    for (int i = 0; i < 8; i++) {
        int gm = m0 + tr + i;
        if (gm >= M) continue;
        #pragma unroll
        for (int j = 0; j < 8; j++) {
            int gn = n0 + tc + j;
            if (gn >= N) continue;
            float v = acc[i][j] * alpha;
            if (bias) v += bias[gn];
            if (ACT == 1) v = gelu_f(v);
            size_t idx = (size_t)gm*ldc + gn;
            if (ADD) C[idx] += v; else C[idx] = v;
        }
    }
}

// ---------------- RoPE (pairs (d, d+32) per thread; q and k) -----------------
__global__ void rope_k()
{
    int i = blockIdx.x * 256 + threadIdx.x;
    if (i >= Ntok*NHx*32) return;
    int d = i & 31;
    int rest = i >> 5;
    int head = rest % NHx;
    int n = rest / NHx;
    int s = n & (Sx-1);
    double inv = exp(-9.210340371976184 * (double)d / 32.0);  // ln(10000)
    double ang = (double)s * inv;
    float c = (float)cos(ang);
    float sn = (float)sin(ang);
    size_t base = (size_t)n*Hx + head*64 + d;
    float a = g_q[base], b2 = g_q[base+32];
    g_q[base]    = a*c - b2*sn;
    g_q[base+32] = b2*c + a*sn;
    a = g_k[base]; b2 = g_k[base+32];
    g_k[base]    = a*c - b2*sn;
    g_k[base+32] = b2*c + a*sn;
}

// ---------------- causal-masked softmax over score rows ----------------------
// Masked lanes use -inf without loading: exp(v - 1e9 - mx) underflows to exactly
// 0.0f in fp32 for any finite score v, so this is bit-identical to the reference
// additive-mask formulation while never touching unwritten (skipped-tile) memory.
__global__ __launch_bounds__(256)
void softmax_k()
{
    int qi = blockIdx.x;
    int z  = blockIdx.y;
    float* row = g_scores + (size_t)z*Sx*Sx + (size_t)qi*Sx;
    __shared__ float red[256];
    int t = threadIdx.x;
    float lv[4];
    float mx = -3.0e38f;
    #pragma unroll
    for (int u = 0; u < 4; u++) {
        int j = t + u*256;
        float v = (j > qi) ? -INFINITY : row[j];
        lv[u] = v; mx = fmaxf(mx, v);
    }
    red[t] = mx; __syncthreads();
    for (int o = 128; o > 0; o >>= 1) { if (t < o) red[t] = fmaxf(red[t], red[t+o]); __syncthreads(); }
    mx = red[0]; __syncthreads();
    float sum = 0.f;
    #pragma unroll
    for (int u = 0; u < 4; u++) { lv[u] = expf(lv[u]-mx); sum += lv[u]; }
    red[t] = sum; __syncthreads();
    for (int o = 128; o > 0; o >>= 1) { if (t < o) red[t] += red[t+o]; __syncthreads(); }
    float inv = 1.0f / red[0];
    #pragma unroll
    for (int u = 0; u < 4; u++) row[t + u*256] = lv[u]*inv;
}

// ---------------- MoE router: softmax + top-2 + renorm -----------------------
__global__ void router_k(const float* __restrict__ Hin, const float* __restrict__ Wr,
                         const float* __restrict__ br)
{
    int warp = threadIdx.x >> 5, lane = threadIdx.x & 31;
    int n = blockIdx.x * 8 + warp;
    if (n >= Ntok) return;
    const float* hr = Hin + (size_t)n*Hx;
    float p[Ex];
    #pragma unroll
    for (int e = 0; e < Ex; e++) {
        float s = 0.f;
        for (int i = lane; i < Hx; i += 32) s = fmaf(hr[i], Wr[i*Ex + e], s);
        #pragma unroll
        for (int o = 16; o > 0; o >>= 1) s += __shfl_xor_sync(0xffffffffu, s, o);
        p[e] = s + br[e];
    }
    if (lane == 0) {
        float m = p[0];
        #pragma unroll
        for (int e = 1; e < Ex; e++) m = fmaxf(m, p[e]);
        float sum = 0.f;
        #pragma unroll
        for (int e = 0; e < Ex; e++) { p[e] = expf(p[e]-m); sum += p[e]; }
        float is = 1.0f/sum;
        #pragma unroll
        for (int e = 0; e < Ex; e++) p[e] *= is;
        int i1 = 0;
        #pragma unroll
        for (int e = 1; e < Ex; e++) if (p[e] > p[i1]) i1 = e;   // earliest on ties
        int i2 = (i1 == 0) ? 1 : 0;
        #pragma unroll
        for (int e = 0; e < Ex; e++) { if (e == i1 || e == i2) continue; if (p[e] > p[i2]) i2 = e; }
        float t1 = p[i1], t2 = p[i2];
        float isum = 1.0f / (t1 + t2 + 1e-9f);
        g_ti[n*2] = i1;  g_ti[n*2+1] = i2;
        g_tp[n*2] = t1*isum; g_tp[n*2+1] = t2*isum;
    }
}

__global__ void zero_k() { int t = threadIdx.x; if (t < Ex) { g_cnt[t] = 0; g_fill[t] = 0; } }
__global__ void count_k() { int i = blockIdx.x*256+threadIdx.x; if (i < NSLOT) atomicAdd(&g_cnt[g_ti[i]], 1); }
__global__ void scan_k()  { g_off[0] = 0; for (int e = 0; e < Ex; e++) g_off[e+1] = g_off[e] + g_cnt[e]; }
__global__ void scatter_k()
{
    int i = blockIdx.x*256+threadIdx.x;
    if (i >= NSLOT) return;
    int e = g_ti[i];
    int pos = atomicAdd(&g_fill[e], 1);
    int slot = g_off[e] + pos;
    g_slot_tok[slot] = i >> 1;
    g_tok2slot[i] = slot;
}

// ---------------- MoE expert GEMM stage 1: act = gelu(h_gather @ W1[e] + b1) -
__global__ __launch_bounds__(256)
void moe1_k(const float* __restrict__ Hin, const float* __restrict__ W1l,
            const float* __restrict__ b1l)
{
    int e = blockIdx.z;
    int base = g_off[e];
    int cnt  = g_off[e+1] - base;
    int m0 = blockIdx.y * BM;
    if (m0 >= cnt) return;
    const float* B    = W1l + (size_t)e*Hx*Fx;
    const float* bias = b1l + (size_t)e*Fx;
    int n0 = blockIdx.x * BN;
    __shared__ __align__(16) float As[BKK][BM];
    __shared__ __align__(16) float Bs[BKK][BN];
    int tid = threadIdx.x;
    int arow = tid >> 1, acol = (tid & 1) * 4;
    int bk = tid >> 5, bn = (tid & 31) * 4;
    int tr = (tid >> 4) << 3, tc = (tid & 15) << 3;
    int r = m0 + arow;
    const float* Arow = nullptr;
    if (r < cnt) Arow = Hin + (size_t)g_slot_tok[base + r]*Hx;
    float acc[8][8];
    #pragma unroll
    for (int i = 0; i < 8; i++)
        #pragma unroll
        for (int j = 0; j < 8; j++) acc[i][j] = 0.f;

    for (int k0 = 0; k0 < Hx; k0 += BKK) {
        float4 av = make_float4(0.f,0.f,0.f,0.f);
        if (Arow) av = *(const float4*)&Arow[k0 + acol];
        As[acol+0][arow] = av.x; As[acol+1][arow] = av.y;
        As[acol+2][arow] = av.z; As[acol+3][arow] = av.w;
        float4 bv = *(const float4*)&B[(size_t)(k0+bk)*Fx + n0 + bn];
        *(float4*)&Bs[bk][bn] = bv;
        __syncthreads();
        #pragma unroll
        for (int kk = 0; kk < BKK; kk++) {
            float a[8], b[8];
            #pragma unroll
            for (int i = 0; i < 8; i++) a[i] = As[kk][tr+i];
            #pragma unroll
            for (int j = 0; j < 8; j++) b[j] = Bs[kk][tc+j];
            #pragma unroll
            for (int i = 0; i < 8; i++)
                #pragma unroll
                for (int j = 0; j < 8; j++)
                    acc[i][j] = fmaf(a[i], b[j], acc[i][j]);
        }
        __syncthreads();
    }
    #pragma unroll
    for (int i = 0; i < 8; i++) {
        int lr = m0 + tr + i;
        if (lr >= cnt) continue;
        #pragma unroll
        for (int j = 0; j < 8; j++) {
            int gn = n0 + tc + j;
            float v = acc[i][j] + bias[gn];
            g_act[(size_t)(base+lr)*Fx + gn] = gelu_f(v);
        }
    }
}

// ---------------- MoE expert GEMM stage 2: oe = act @ W2[e] + b2 -------------
__global__ __launch_bounds__(256)
void moe2_k(const float* __restrict__ W2l, const float* __restrict__ b2l)
{
    int e = blockIdx.z;
    int base = g_off[e];
    int cnt  = g_off[e+1] - base;
    int m0 = blockIdx.y * BM;
    if (m0 >= cnt) return;
    const float* B    = W2l + (size_t)e*Fx*Hx;
    const float* bias = b2l + (size_t)e*Hx;
    int n0 = blockIdx.x * BN;
    __shared__ __align__(16) float As[BKK][BM];
    __shared__ __align__(16) float Bs[BKK][BN];
    int tid = threadIdx.x;
    int arow = tid >> 1, acol = (tid & 1) * 4;
    int bk = tid >> 5, bn = (tid & 31) * 4;
    int tr = (tid >> 4) << 3, tc = (tid & 15) << 3;
    int r = m0 + arow;
    const float* Arow = nullptr;
    if (r < cnt) Arow = g_act + (size_t)(base + r)*Fx;
    float acc[8][8];
    #pragma unroll
    for (int i = 0; i < 8; i++)
        #pragma unroll
        for (int j = 0; j < 8; j++) acc[i][j] = 0.f;

    for (int k0 = 0; k0 < Fx; k0 += BKK) {
        float4 av = make_float4(0.f,0.f,0.f,0.f);
        if (Arow) av = *(const float4*)&Arow[k0 + acol];
        As[acol+0][arow] = av.x; As[acol+1][arow] = av.y;
        As[acol+2][arow] = av.z; As[acol+3][arow] = av.w;
        float4 bv = make_float4(0.f,0.f,0.f,0.f);
        if (n0 + bn < Hx) bv = *(const float4*)&B[(size_t)(k0+bk)*Hx + n0 + bn];
        *(float4*)&Bs[bk][bn] = bv;
        __syncthreads();
        #pragma unroll
        for (int kk = 0; kk < BKK; kk++) {
            float a[8], b[8];
            #pragma unroll
            for (int i = 0; i < 8; i++) a[i] = As[kk][tr+i];
            #pragma unroll
            for (int j = 0; j < 8; j++) b[j] = Bs[kk][tc+j];
            #pragma unroll
            for (int i = 0; i < 8; i++)
                #pragma unroll
                for (int j = 0; j < 8; j++)
                    acc[i][j] = fmaf(a[i], b[j], acc[i][j]);
        }
        __syncthreads();
    }
    #pragma unroll
    for (int i = 0; i < 8; i++) {
        int lr = m0 + tr + i;
        if (lr >= cnt) continue;
        #pragma unroll
        for (int j = 0; j < 8; j++) {
            int gn = n0 + tc + j;
            if (gn >= Hx) continue;
            g_oe[(size_t)(base+lr)*Hx + gn] = acc[i][j] + bias[gn];
        }
    }
}

// ---------------- combine: x += w0*oe[slot0] + w1*oe[slot1] (deterministic) --
__global__ void combine_k()
{
    int i = blockIdx.x*256+threadIdx.x;
    if (i >= Ntok*Hx) return;
    int n = i / Hx, hh = i % Hx;
    int s0 = g_tok2slot[n*2], s1 = g_tok2slot[n*2+1];
    g_x[i] += g_tp[n*2]  * g_oe[(size_t)s0*Hx + hh]
            + g_tp[n*2+1]* g_oe[(size_t)s1*Hx + hh];
}

// ---------------- host orchestration ----------------------------------------
extern "C" void kernel_launch(void* const* d_in, const int* in_sizes, int n_in,
                              void* d_out, int out_size)
{
    const int*   ids  = (const int*)  d_in[0];
    const float* emb  = (const float*)d_in[1];
    const float* ln1w = (const float*)d_in[2];
    const float* ln1b = (const float*)d_in[3];
    const float* ln2w = (const float*)d_in[4];
    const float* ln2b = (const float*)d_in[5];
    const float* lnfw = (const float*)d_in[6];
    const float* lnfb = (const float*)d_in[7];
    const float* Wq   = (const float*)d_in[8];
    const float* bq   = (const float*)d_in[9];
    const float* Wk   = (const float*)d_in[10];
    const float* bkb  = (const float*)d_in[11];
    const float* Wv   = (const float*)d_in[12];
    const float* bv   = (const float*)d_in[13];
    const float* Wo   = (const float*)d_in[14];
    const float* bo   = (const float*)d_in[15];
    const float* Wr   = (const float*)d_in[16];
    const float* br   = (const float*)d_in[17];
    const float* W1   = (const float*)d_in[18];
    const float* b1   = (const float*)d_in[19];
    const float* W2   = (const float*)d_in[20];
    const float* b2   = (const float*)d_in[21];
    float* out = (float*)d_out;

    float *px, *ph, *pq, *pk, *pv, *pa, *ps;
    cudaGetSymbolAddress((void**)&px, g_x);
    cudaGetSymbolAddress((void**)&ph, g_h);
    cudaGetSymbolAddress((void**)&pq, g_q);
    cudaGetSymbolAddress((void**)&pk, g_k);
    cudaGetSymbolAddress((void**)&pv, g_v);
    cudaGetSymbolAddress((void**)&pa, g_att);
    cudaGetSymbolAddress((void**)&ps, g_scores);

    embed_k<<<(Ntok*Hx + 255)/256, 256>>>(ids, emb);

    for (int l = 0; l < Lx; l++) {
        ln_k<<<Ntok, 256>>>(px, ln1w + l*Hx, ln1b + l*Hx, ph);

        dim3 gp(Hx/BN, Ntok/BM, 1);  // (6,16)
        gemm_k<0,0,0><<<gp,256>>>(ph, Wq + (size_t)l*Hx*Hx, bq + l*Hx, pq,
            Ntok, Hx, Hx, Hx, Hx, Hx, 1.f, 0, 0,0,0,0,0,0);
        gemm_k<0,0,0><<<gp,256>>>(ph, Wk + (size_t)l*Hx*Hx, bkb + l*Hx, pk,
            Ntok, Hx, Hx, Hx, Hx, Hx, 1.f, 0, 0,0,0,0,0,0);
        gemm_k<0,0,0><<<gp,256>>>(ph, Wv + (size_t)l*Hx*Hx, bv + l*Hx, pv,
            Ntok, Hx, Hx, Hx, Hx, Hx, 1.f, 0, 0,0,0,0,0,0);

        rope_k<<<(Ntok*NHx*32 + 255)/256, 256>>>();

        dim3 gs(Sx/BN, Sx/BM, Bx*NHx);  // (8,8,24); above-diagonal tiles early-exit
        gemm_k<1,0,0,1,0><<<gs,256>>>(pq, pk, nullptr, ps,
            Sx, Sx, HDx, Hx, Hx, Sx, 0.125f,
            NHx, (long long)Sx*Hx, 64, (long long)Sx*Hx, 64,
            (long long)NHx*Sx*Sx, (long long)Sx*Sx);

        softmax_k<<<dim3(Sx, Bx*NHx), 256>>>();

        dim3 gpv(1, Sx/BM, Bx*NHx);  // K loop clamped to m0+128 (causal zeros)
        gemm_k<0,0,0,0,1><<<gpv,256>>>(ps, pv, nullptr, pa,
            Sx, HDx, Sx, Sx, Hx, Hx, 1.f,
            NHx, (long long)NHx*Sx*Sx, (long long)Sx*Sx,
            (long long)Sx*Hx, 64, (long long)Sx*Hx, 64);

        gemm_k<0,0,1><<<gp,256>>>(pa, Wo + (size_t)l*Hx*Hx, bo + l*Hx, px,
            Ntok, Hx, Hx, Hx, Hx, Hx, 1.f, 0, 0,0,0,0,0,0);

        // ---- MoE ----
        ln_k<<<Ntok, 256>>>(px, ln2w + l*Hx, ln2b + l*Hx, ph);
        router_k<<<Ntok/8, 256>>>(ph, Wr + (size_t)l*Hx*Ex, br + l*Ex);
        zero_k<<<1, 32>>>();
        count_k<<<NSLOT/256, 256>>>();
        scan_k<<<1, 1>>>();
        scatter_k<<<NSLOT/256, 256>>>();
        moe1_k<<<dim3(Fx/BN, Ntok/BM, Ex), 256>>>(ph, W1 + (size_t)l*Ex*Hx*Fx, b1 + (size_t)l*Ex*Fx);
        moe2_k<<<dim3(Hx/BN, Ntok/BM, Ex), 256>>>(W2 + (size_t)l*Ex*Fx*Hx, b2 + (size_t)l*Ex*Hx);
        combine_k<<<(Ntok*Hx + 255)/256, 256>>>();
    }

    ln_k<<<Ntok, 256>>>(px, lnfw, lnfb, ph);
    dim3 glm((Vx + BN - 1)/BN, Ntok/BM, 1);  // (393,16)
    gemm_k<1,0,0><<<glm,256>>>(ph, emb, nullptr, out,
        Ntok, Vx, Hx, Hx, Hx, Vx, 1.f, 0, 0,0,0,0,0,0);
}

// round 8
// speedup vs baseline: 1.2215x; 1.2215x over previous
#include <cuda_runtime.h>
#include <cuda_bf16.h>
#include <math.h>
#include <stdint.h>

#define Lx   2
#define Bx   2
#define Sx   1024
#define Hx   768
#define NHx  12
#define HDx  64
#define Ex   8
#define KKx  2
#define Fx   3072
#define Vx   50257
#define Ntok (Bx*Sx)          /* 2048 */
#define NSLOT (Ntok*KKx)      /* 4096 */
#define EPSx 1e-5f

#define BM 128
#define BN 128
#define BKK 8

// ---------------- scratch (static __device__ arrays; allocation-free) -------
__device__ float g_x[Ntok*Hx];
__device__ float g_h[Ntok*Hx];
__device__ float g_q[Ntok*Hx];
__device__ float g_k[Ntok*Hx];
__device__ float g_v[Ntok*Hx];
__device__ float g_att[Ntok*Hx];
__device__ float g_scores[(size_t)Bx*NHx*Sx*Sx];   // ~100 MB
__device__ float g_act[(size_t)NSLOT*Fx];          // ~50 MB
__device__ float g_oe[(size_t)NSLOT*Hx];
__device__ float g_tp[NSLOT];
__device__ int   g_ti[NSLOT];
__device__ int   g_cnt[Ex];
__device__ int   g_off[Ex+1];
__device__ int   g_fill[Ex];
__device__ int   g_slot_tok[NSLOT];
__device__ int   g_tok2slot[NSLOT];
// bf16-split operands for the tensor-core LM head
__device__ __nv_bfloat16 g_h_hi[Ntok*Hx];
__device__ __nv_bfloat16 g_h_lo[Ntok*Hx];
__device__ __nv_bfloat16 g_emb_hi[(size_t)Vx*Hx];
__device__ __nv_bfloat16 g_emb_lo[(size_t)Vx*Hx];

__device__ __forceinline__ float gelu_f(float x) {
    return 0.5f * x * (1.0f + erff(x * 0.70710678118654752440f));
}

__device__ __forceinline__ uint32_t smem_u32(const void* p) {
    uint32_t a;
    asm("{ .reg .u64 t; cvta.to.shared.u64 t, %1; cvt.u32.u64 %0, t; }" : "=r"(a) : "l"(p));
    return a;
}
__device__ __forceinline__ void ldmx4(uint32_t* r, uint32_t addr) {
    asm volatile("ldmatrix.sync.aligned.m8n8.x4.shared.b16 {%0,%1,%2,%3}, [%4];"
        : "=r"(r[0]), "=r"(r[1]), "=r"(r[2]), "=r"(r[3]) : "r"(addr));
}
__device__ __forceinline__ void mma16816(float* d, const uint32_t* a, uint32_t b0, uint32_t b1) {
    asm volatile("mma.sync.aligned.m16n8k16.row.col.f32.bf16.bf16.f32 "
        "{%0,%1,%2,%3}, {%4,%5,%6,%7}, {%8,%9}, {%0,%1,%2,%3};"
        : "+f"(d[0]), "+f"(d[1]), "+f"(d[2]), "+f"(d[3])
        : "r"(a[0]), "r"(a[1]), "r"(a[2]), "r"(a[3]), "r"(b0), "r"(b1));
}

// ---------------- embedding gather ------------------------------------------
__global__ void embed_k(const int* __restrict__ ids, const float* __restrict__ emb)
{
    int i = blockIdx.x * 256 + threadIdx.x;
    if (i >= Ntok*Hx) return;
    int n = i / Hx, hh = i % Hx;
    g_x[i] = emb[(size_t)ids[n]*Hx + hh];
}

// ---------------- bf16 split: x = hi + lo ------------------------------------
__global__ void split_k(const float* __restrict__ X, __nv_bfloat16* __restrict__ hi,
                        __nv_bfloat16* __restrict__ lo, size_t n)
{
    size_t i = (size_t)blockIdx.x * 256 + threadIdx.x;
    if (i >= n) return;
    float v = X[i];
    __nv_bfloat16 h = __float2bfloat16_rn(v);
    hi[i] = h;
    lo[i] = __float2bfloat16_rn(v - __bfloat162float(h));
}

// ---------------- layernorm (one block per token) ---------------------------
__global__ __launch_bounds__(256)
void ln_k(const float* __restrict__ X, const float* __restrict__ w,
          const float* __restrict__ b, float* __restrict__ Y)
{
    int n = blockIdx.x;
    __shared__ float sx[Hx];
    __shared__ float red[256];
    const float* xr = X + (size_t)n*Hx;
    int t = threadIdx.x;
    float s = 0.f;
    for (int i = t; i < Hx; i += 256) { float v = xr[i]; sx[i] = v; s += v; }
    red[t] = s; __syncthreads();
    for (int o = 128; o > 0; o >>= 1) { if (t < o) red[t] += red[t+o]; __syncthreads(); }
    float mean = red[0] * (1.0f/Hx);
    __syncthreads();
    float s2 = 0.f;
    for (int i = t; i < Hx; i += 256) { float d = sx[i]-mean; s2 += d*d; }
    __syncthreads();
    red[t] = s2; __syncthreads();
    for (int o = 128; o > 0; o >>= 1) { if (t < o) red[t] += red[t+o]; __syncthreads(); }
    float inv = rsqrtf(red[0] * (1.0f/Hx) + EPSx);
    for (int i = t; i < Hx; i += 256)
        Y[(size_t)n*Hx + i] = (sx[i]-mean)*inv*w[i] + b[i];
}

// ---------------- generic tiled SGEMM ---------------------------------------
template<int TB, int ACT, int ADD, int CSKIP = 0, int KCLAMP = 0>
__global__ __launch_bounds__(256)
void gemm_k(const float* __restrict__ A, const float* __restrict__ B,
            const float* __restrict__ bias, float* __restrict__ C,
            int M, int N, int Kd, int lda, int ldb, int ldc, float alpha,
            int zdiv, long long sAb, long long sAh, long long sBb, long long sBh,
            long long sCb, long long sCh)
{
    const int m0 = blockIdx.y * BM;
    const int n0 = blockIdx.x * BN;
    if (CSKIP && n0 > m0) return;
    if (KCLAMP && m0 + BM < Kd) Kd = m0 + BM;
    if (zdiv > 0) {
        int z = blockIdx.z;
        int zb = z / zdiv, zh = z % zdiv;
        A += (long long)zb*sAb + (long long)zh*sAh;
        B += (long long)zb*sBb + (long long)zh*sBh;
        C += (long long)zb*sCb + (long long)zh*sCh;
    }
    __shared__ __align__(16) float As[BKK][BM];
    __shared__ __align__(16) float Bs[BKK][BN];
    const int tid = threadIdx.x;
    const int arow = tid >> 1, acol = (tid & 1) * 4;
    const int tr = (tid >> 4) << 3;
    const int tc = (tid & 15) << 3;

    float acc[8][8];
    #pragma unroll
    for (int i = 0; i < 8; i++)
        #pragma unroll
        for (int j = 0; j < 8; j++) acc[i][j] = 0.f;

    for (int k0 = 0; k0 < Kd; k0 += BKK) {
        {
            int gm = m0 + arow;
            float4 av = make_float4(0.f,0.f,0.f,0.f);
            if (gm < M) av = *(const float4*)&A[(size_t)gm*lda + k0 + acol];
            As[acol+0][arow] = av.x; As[acol+1][arow] = av.y;
            As[acol+2][arow] = av.z; As[acol+3][arow] = av.w;
        }
        if (TB) {
            int bn = tid >> 1, bk = (tid & 1) * 4;
            int gn = n0 + bn;
            float4 bv = make_float4(0.f,0.f,0.f,0.f);
            if (gn < N) bv = *(const float4*)&B[(size_t)gn*ldb + k0 + bk];
            Bs[bk+0][bn] = bv.x; Bs[bk+1][bn] = bv.y;
            Bs[bk+2][bn] = bv.z; Bs[bk+3][bn] = bv.w;
        } else {
            int bk = tid >> 5, bn = (tid & 31) * 4;
            int gn = n0 + bn;
            float4 bv = make_float4(0.f,0.f,0.f,0.f);
            if (gn < N) bv = *(const float4*)&B[(size_t)(k0+bk)*ldb + gn];
            *(float4*)&Bs[bk][bn] = bv;
        }
        __syncthreads();
        #pragma unroll
        for (int kk = 0; kk < BKK; kk++) {
            float a[8], b[8];
            #pragma unroll
            for (int i = 0; i < 8; i++) a[i] = As[kk][tr+i];
            #pragma unroll
            for (int j = 0; j < 8; j++) b[j] = Bs[kk][tc+j];
            #pragma unroll
            for (int i = 0; i < 8; i++)
                #pragma unroll
                for (int j = 0; j < 8; j++)
                    acc[i][j] = fmaf(a[i], b[j], acc[i][j]);
        }
        __syncthreads();
    }
    #pragma unroll
    for (int i = 0; i < 8; i++) {
        int gm = m0 + tr + i;
        if (gm >= M) continue;
        #pragma unroll
        for (int j = 0; j < 8; j++) {
            int gn = n0 + tc + j;
            if (gn >= N) continue;
            float v = acc[i][j] * alpha;
            if (bias) v += bias[gn];
            if (ACT == 1) v = gelu_f(v);
            size_t idx = (size_t)gm*ldc + gn;
            if (ADD) C[idx] += v; else C[idx] = v;
        }
    }
}

// ---------------- bf16-split HMMA LM head ------------------------------------
// C[2048, 50257] = h @ emb^T via Ahi*Bhi + Ahi*Blo + Alo*Bhi (fp32 accum)
#define LM_BK  32
#define LM_LDS 40                     /* 32 + 8 pad; conflict-free for ldmatrix */

__global__ __launch_bounds__(256)
void lmhead_hmma_k(float* __restrict__ C)
{
    __shared__ __nv_bfloat16 sAhi[128][LM_LDS], sAlo[128][LM_LDS];
    __shared__ __nv_bfloat16 sBhi[128][LM_LDS], sBlo[128][LM_LDS];
    const int tid = threadIdx.x;
    const int wid = tid >> 5, lane = tid & 31;
    const int m0 = blockIdx.x * 128;
    const int n0 = blockIdx.y * 128;
    const int wm = (wid & 3) * 32;     // warp tile: 32 (m) x 64 (n)
    const int wn = (wid >> 2) * 64;

    float acc[2][8][4];
    #pragma unroll
    for (int mt = 0; mt < 2; mt++)
        #pragma unroll
        for (int nt = 0; nt < 8; nt++)
            #pragma unroll
            for (int r = 0; r < 4; r++) acc[mt][nt][r] = 0.f;

    const int lrow = tid >> 1;          // 0..127
    const int lcol = (tid & 1) * 16;    // 0 or 16 bf16

    // ldmatrix source addresses (per-lane row/col within tiles)
    const int a_r = lane & 15, a_c = (lane >> 4) * 8;
    const int b_r = (lane & 7) + ((lane >> 4) & 1) * 8;
    const int b_c = ((lane >> 3) & 1) * 8;

    for (int kc = 0; kc < Hx/LM_BK; kc++) {
        const int kg = kc * LM_BK + lcol;
        {   // A tiles (always in range: M=2048 multiple of 128)
            const uint4* s = (const uint4*)&g_h_hi[(size_t)(m0+lrow)*Hx + kg];
            *(uint4*)&sAhi[lrow][lcol]   = s[0];
            *(uint4*)&sAhi[lrow][lcol+8] = s[1];
            s = (const uint4*)&g_h_lo[(size_t)(m0+lrow)*Hx + kg];
            *(uint4*)&sAlo[lrow][lcol]   = s[0];
            *(uint4*)&sAlo[lrow][lcol+8] = s[1];
        }
        {   // B tiles, zero-padded past Vx
            int n = n0 + lrow;
            uint4 h0 = make_uint4(0,0,0,0), h1 = h0, l0 = h0, l1 = h0;
            if (n < Vx) {
                const uint4* s = (const uint4*)&g_emb_hi[(size_t)n*Hx + kg];
                h0 = s[0]; h1 = s[1];
                s = (const uint4*)&g_emb_lo[(size_t)n*Hx + kg];
                l0 = s[0]; l1 = s[1];
            }
            *(uint4*)&sBhi[lrow][lcol]   = h0;
            *(uint4*)&sBhi[lrow][lcol+8] = h1;
            *(uint4*)&sBlo[lrow][lcol]   = l0;
            *(uint4*)&sBlo[lrow][lcol+8] = l1;
        }
        __syncthreads();
        #pragma unroll
        for (int pass = 0; pass < 3; pass++) {
            const __nv_bfloat16 (*pA)[LM_LDS] = (pass == 2) ? sAlo : sAhi;
            const __nv_bfloat16 (*pB)[LM_LDS] = (pass == 1) ? sBlo : sBhi;
            #pragma unroll
            for (int ks = 0; ks < 2; ks++) {
                const int k0 = ks * 16;
                uint32_t af[2][4];
                #pragma unroll
                for (int mt = 0; mt < 2; mt++)
                    ldmx4(af[mt], smem_u32(&pA[wm + mt*16 + a_r][k0 + a_c]));
                uint32_t bf[4][4];
                #pragma unroll
                for (int bq = 0; bq < 4; bq++)
                    ldmx4(bf[bq], smem_u32(&pB[wn + bq*16 + b_r][k0 + b_c]));
                #pragma unroll
                for (int mt = 0; mt < 2; mt++)
                    #pragma unroll
                    for (int nt = 0; nt < 8; nt++)
                        mma16816(acc[mt][nt], af[mt],
                                 bf[nt >> 1][(nt & 1)*2], bf[nt >> 1][(nt & 1)*2 + 1]);
            }
        }
        __syncthreads();
    }

    // epilogue: fragment -> gmem (lane l: rows +l/4, +l/4+8; cols +(l%4)*2)
    const int er = lane >> 2, ec = (lane & 3) * 2;
    #pragma unroll
    for (int mt = 0; mt < 2; mt++) {
        #pragma unroll
        for (int nt = 0; nt < 8; nt++) {
            int row = m0 + wm + mt*16 + er;
            int col = n0 + wn + nt*8 + ec;
            if (col < Vx) {
                C[(size_t)row*Vx + col] = acc[mt][nt][0];
                C[(size_t)(row+8)*Vx + col] = acc[mt][nt][2];
            }
            if (col + 1 < Vx) {
                C[(size_t)row*Vx + col + 1] = acc[mt][nt][1];
                C[(size_t)(row+8)*Vx + col + 1] = acc[mt][nt][3];
            }
        }
    }
}

// ---------------- RoPE (pairs (d, d+32) per thread; q and k) -----------------
__global__ void rope_k()
{
    int i = blockIdx.x * 256 + threadIdx.x;
    if (i >= Ntok*NHx*32) return;
    int d = i & 31;
    int rest = i >> 5;
    int head = rest % NHx;
    int n = rest / NHx;
    int s = n & (Sx-1);
    double inv = exp(-9.210340371976184 * (double)d / 32.0);  // ln(10000)
    double ang = (double)s * inv;
    float c = (float)cos(ang);
    float sn = (float)sin(ang);
    size_t base = (size_t)n*Hx + head*64 + d;
    float a = g_q[base], b2 = g_q[base+32];
    g_q[base]    = a*c - b2*sn;
    g_q[base+32] = b2*c + a*sn;
    a = g_k[base]; b2 = g_k[base+32];
    g_k[base]    = a*c - b2*sn;
    g_k[base+32] = b2*c + a*sn;
}

// ---------------- causal-masked softmax over score rows ----------------------
__global__ __launch_bounds__(256)
void softmax_k()
{
    int qi = blockIdx.x;
    int z  = blockIdx.y;
    float* row = g_scores + (size_t)z*Sx*Sx + (size_t)qi*Sx;
    __shared__ float red[256];
    int t = threadIdx.x;
    float lv[4];
    float mx = -3.0e38f;
    #pragma unroll
    for (int u = 0; u < 4; u++) {
        int j = t + u*256;
        float v = (j > qi) ? -INFINITY : row[j];
        lv[u] = v; mx = fmaxf(mx, v);
    }
    red[t] = mx; __syncthreads();
    for (int o = 128; o > 0; o >>= 1) { if (t < o) red[t] = fmaxf(red[t], red[t+o]); __syncthreads(); }
    mx = red[0]; __syncthreads();
    float sum = 0.f;
    #pragma unroll
    for (int u = 0; u < 4; u++) { lv[u] = expf(lv[u]-mx); sum += lv[u]; }
    red[t] = sum; __syncthreads();
    for (int o = 128; o > 0; o >>= 1) { if (t < o) red[t] += red[t+o]; __syncthreads(); }
    float inv = 1.0f / red[0];
    #pragma unroll
    for (int u = 0; u < 4; u++) row[t + u*256] = lv[u]*inv;
}

// ---------------- MoE router: softmax + top-2 + renorm -----------------------
__global__ void router_k(const float* __restrict__ Hin, const float* __restrict__ Wr,
                         const float* __restrict__ br)
{
    int warp = threadIdx.x >> 5, lane = threadIdx.x & 31;
    int n = blockIdx.x * 8 + warp;
    if (n >= Ntok) return;
    const float* hr = Hin + (size_t)n*Hx;
    float p[Ex];
    #pragma unroll
    for (int e = 0; e < Ex; e++) {
        float s = 0.f;
        for (int i = lane; i < Hx; i += 32) s = fmaf(hr[i], Wr[i*Ex + e], s);
        #pragma unroll
        for (int o = 16; o > 0; o >>= 1) s += __shfl_xor_sync(0xffffffffu, s, o);
        p[e] = s + br[e];
    }
    if (lane == 0) {
        float m = p[0];
        #pragma unroll
        for (int e = 1; e < Ex; e++) m = fmaxf(m, p[e]);
        float sum = 0.f;
        #pragma unroll
        for (int e = 0; e < Ex; e++) { p[e] = expf(p[e]-m); sum += p[e]; }
        float is = 1.0f/sum;
        #pragma unroll
        for (int e = 0; e < Ex; e++) p[e] *= is;
        int i1 = 0;
        #pragma unroll
        for (int e = 1; e < Ex; e++) if (p[e] > p[i1]) i1 = e;
        int i2 = (i1 == 0) ? 1 : 0;
        #pragma unroll
        for (int e = 0; e < Ex; e++) { if (e == i1 || e == i2) continue; if (p[e] > p[i2]) i2 = e; }
        float t1 = p[i1], t2 = p[i2];
        float isum = 1.0f / (t1 + t2 + 1e-9f);
        g_ti[n*2] = i1;  g_ti[n*2+1] = i2;
        g_tp[n*2] = t1*isum; g_tp[n*2+1] = t2*isum;
    }
}

__global__ void zero_k() { int t = threadIdx.x; if (t < Ex) { g_cnt[t] = 0; g_fill[t] = 0; } }
__global__ void count_k() { int i = blockIdx.x*256+threadIdx.x; if (i < NSLOT) atomicAdd(&g_cnt[g_ti[i]], 1); }
__global__ void scan_k()  { g_off[0] = 0; for (int e = 0; e < Ex; e++) g_off[e+1] = g_off[e] + g_cnt[e]; }
__global__ void scatter_k()
{
    int i = blockIdx.x*256+threadIdx.x;
    if (i >= NSLOT) return;
    int e = g_ti[i];
    int pos = atomicAdd(&g_fill[e], 1);
    int slot = g_off[e] + pos;
    g_slot_tok[slot] = i >> 1;
    g_tok2slot[i] = slot;
}

// ---------------- MoE expert GEMM stage 1 ------------------------------------
__global__ __launch_bounds__(256)
void moe1_k(const float* __restrict__ Hin, const float* __restrict__ W1l,
            const float* __restrict__ b1l)
{
    int e = blockIdx.z;
    int base = g_off[e];
    int cnt  = g_off[e+1] - base;
    int m0 = blockIdx.y * BM;
    if (m0 >= cnt) return;
    const float* B    = W1l + (size_t)e*Hx*Fx;
    const float* bias = b1l + (size_t)e*Fx;
    int n0 = blockIdx.x * BN;
    __shared__ __align__(16) float As[BKK][BM];
    __shared__ __align__(16) float Bs[BKK][BN];
    int tid = threadIdx.x;
    int arow = tid >> 1, acol = (tid & 1) * 4;
    int bk = tid >> 5, bn = (tid & 31) * 4;
    int tr = (tid >> 4) << 3, tc = (tid & 15) << 3;
    int r = m0 + arow;
    const float* Arow = nullptr;
    if (r < cnt) Arow = Hin + (size_t)g_slot_tok[base + r]*Hx;
    float acc[8][8];
    #pragma unroll
    for (int i = 0; i < 8; i++)
        #pragma unroll
        for (int j = 0; j < 8; j++) acc[i][j] = 0.f;

    for (int k0 = 0; k0 < Hx; k0 += BKK) {
        float4 av = make_float4(0.f,0.f,0.f,0.f);
        if (Arow) av = *(const float4*)&Arow[k0 + acol];
        As[acol+0][arow] = av.x; As[acol+1][arow] = av.y;
        As[acol+2][arow] = av.z; As[acol+3][arow] = av.w;
        float4 bv = *(const float4*)&B[(size_t)(k0+bk)*Fx + n0 + bn];
        *(float4*)&Bs[bk][bn] = bv;
        __syncthreads();
        #pragma unroll
        for (int kk = 0; kk < BKK; kk++) {
            float a[8], b[8];
            #pragma unroll
            for (int i = 0; i < 8; i++) a[i] = As[kk][tr+i];
            #pragma unroll
            for (int j = 0; j < 8; j++) b[j] = Bs[kk][tc+j];
            #pragma unroll
            for (int i = 0; i < 8; i++)
                #pragma unroll
                for (int j = 0; j < 8; j++)
                    acc[i][j] = fmaf(a[i], b[j], acc[i][j]);
        }
        __syncthreads();
    }
    #pragma unroll
    for (int i = 0; i < 8; i++) {
        int lr = m0 + tr + i;
        if (lr >= cnt) continue;
        #pragma unroll
        for (int j = 0; j < 8; j++) {
            int gn = n0 + tc + j;
            float v = acc[i][j] + bias[gn];
            g_act[(size_t)(base+lr)*Fx + gn] = gelu_f(v);
        }
    }
}

// ---------------- MoE expert GEMM stage 2 ------------------------------------
__global__ __launch_bounds__(256)
void moe2_k(const float* __restrict__ W2l, const float* __restrict__ b2l)
{
    int e = blockIdx.z;
    int base = g_off[e];
    int cnt  = g_off[e+1] - base;
    int m0 = blockIdx.y * BM;
    if (m0 >= cnt) return;
    const float* B    = W2l + (size_t)e*Fx*Hx;
    const float* bias = b2l + (size_t)e*Hx;
    int n0 = blockIdx.x * BN;
    __shared__ __align__(16) float As[BKK][BM];
    __shared__ __align__(16) float Bs[BKK][BN];
    int tid = threadIdx.x;
    int arow = tid >> 1, acol = (tid & 1) * 4;
    int bk = tid >> 5, bn = (tid & 31) * 4;
    int tr = (tid >> 4) << 3, tc = (tid & 15) << 3;
    int r = m0 + arow;
    const float* Arow = nullptr;
    if (r < cnt) Arow = g_act + (size_t)(base + r)*Fx;
    float acc[8][8];
    #pragma unroll
    for (int i = 0; i < 8; i++)
        #pragma unroll
        for (int j = 0; j < 8; j++) acc[i][j] = 0.f;

    for (int k0 = 0; k0 < Fx; k0 += BKK) {
        float4 av = make_float4(0.f,0.f,0.f,0.f);
        if (Arow) av = *(const float4*)&Arow[k0 + acol];
        As[acol+0][arow] = av.x; As[acol+1][arow] = av.y;
        As[acol+2][arow] = av.z; As[acol+3][arow] = av.w;
        float4 bv = make_float4(0.f,0.f,0.f,0.f);
        if (n0 + bn < Hx) bv = *(const float4*)&B[(size_t)(k0+bk)*Hx + n0 + bn];
        *(float4*)&Bs[bk][bn] = bv;
        __syncthreads();
        #pragma unroll
        for (int kk = 0; kk < BKK; kk++) {
            float a[8], b[8];
            #pragma unroll
            for (int i = 0; i < 8; i++) a[i] = As[kk][tr+i];
            #pragma unroll
            for (int j = 0; j < 8; j++) b[j] = Bs[kk][tc+j];
            #pragma unroll
            for (int i = 0; i < 8; i++)
                #pragma unroll
                for (int j = 0; j < 8; j++)
                    acc[i][j] = fmaf(a[i], b[j], acc[i][j]);
        }
        __syncthreads();
    }
    #pragma unroll
    for (int i = 0; i < 8; i++) {
        int lr = m0 + tr + i;
        if (lr >= cnt) continue;
        #pragma unroll
        for (int j = 0; j < 8; j++) {
            int gn = n0 + tc + j;
            if (gn >= Hx) continue;
            g_oe[(size_t)(base+lr)*Hx + gn] = acc[i][j] + bias[gn];
        }
    }
}

// ---------------- combine ----------------------------------------------------
__global__ void combine_k()
{
    int i = blockIdx.x*256+threadIdx.x;
    if (i >= Ntok*Hx) return;
    int n = i / Hx, hh = i % Hx;
    int s0 = g_tok2slot[n*2], s1 = g_tok2slot[n*2+1];
    g_x[i] += g_tp[n*2]  * g_oe[(size_t)s0*Hx + hh]
            + g_tp[n*2+1]* g_oe[(size_t)s1*Hx + hh];
}

// ---------------- host orchestration ----------------------------------------
extern "C" void kernel_launch(void* const* d_in, const int* in_sizes, int n_in,
                              void* d_out, int out_size)
{
    const int*   ids  = (const int*)  d_in[0];
    const float* emb  = (const float*)d_in[1];
    const float* ln1w = (const float*)d_in[2];
    const float* ln1b = (const float*)d_in[3];
    const float* ln2w = (const float*)d_in[4];
    const float* ln2b = (const float*)d_in[5];
    const float* lnfw = (const float*)d_in[6];
    const float* lnfb = (const float*)d_in[7];
    const float* Wq   = (const float*)d_in[8];
    const float* bq   = (const float*)d_in[9];
    const float* Wk   = (const float*)d_in[10];
    const float* bkb  = (const float*)d_in[11];
    const float* Wv   = (const float*)d_in[12];
    const float* bv   = (const float*)d_in[13];
    const float* Wo   = (const float*)d_in[14];
    const float* bo   = (const float*)d_in[15];
    const float* Wr   = (const float*)d_in[16];
    const float* br   = (const float*)d_in[17];
    const float* W1   = (const float*)d_in[18];
    const float* b1   = (const float*)d_in[19];
    const float* W2   = (const float*)d_in[20];
    const float* b2   = (const float*)d_in[21];
    float* out = (float*)d_out;

    float *px, *ph, *pq, *pk, *pv, *pa, *ps;
    cudaGetSymbolAddress((void**)&px, g_x);
    cudaGetSymbolAddress((void**)&ph, g_h);
    cudaGetSymbolAddress((void**)&pq, g_q);
    cudaGetSymbolAddress((void**)&pk, g_k);
    cudaGetSymbolAddress((void**)&pv, g_v);
    cudaGetSymbolAddress((void**)&pa, g_att);
    cudaGetSymbolAddress((void**)&ps, g_scores);
    __nv_bfloat16 *phh, *phl, *peh, *pel;
    cudaGetSymbolAddress((void**)&phh, g_h_hi);
    cudaGetSymbolAddress((void**)&phl, g_h_lo);
    cudaGetSymbolAddress((void**)&peh, g_emb_hi);
    cudaGetSymbolAddress((void**)&pel, g_emb_lo);

    embed_k<<<(Ntok*Hx + 255)/256, 256>>>(ids, emb);
    // emb split is input-only; runs once per replay, overlaps nothing critical
    split_k<<<(int)(((size_t)Vx*Hx + 255)/256), 256>>>(emb, peh, pel, (size_t)Vx*Hx);

    for (int l = 0; l < Lx; l++) {
        ln_k<<<Ntok, 256>>>(px, ln1w + l*Hx, ln1b + l*Hx, ph);

        dim3 gp(Hx/BN, Ntok/BM, 1);
        gemm_k<0,0,0><<<gp,256>>>(ph, Wq + (size_t)l*Hx*Hx, bq + l*Hx, pq,
            Ntok, Hx, Hx, Hx, Hx, Hx, 1.f, 0, 0,0,0,0,0,0);
        gemm_k<0,0,0><<<gp,256>>>(ph, Wk + (size_t)l*Hx*Hx, bkb + l*Hx, pk,
            Ntok, Hx, Hx, Hx, Hx, Hx, 1.f, 0, 0,0,0,0,0,0);
        gemm_k<0,0,0><<<gp,256>>>(ph, Wv + (size_t)l*Hx*Hx, bv + l*Hx, pv,
            Ntok, Hx, Hx, Hx, Hx, Hx, 1.f, 0, 0,0,0,0,0,0);

        rope_k<<<(Ntok*NHx*32 + 255)/256, 256>>>();

        dim3 gs(Sx/BN, Sx/BM, Bx*NHx);
        gemm_k<1,0,0,1,0><<<gs,256>>>(pq, pk, nullptr, ps,
            Sx, Sx, HDx, Hx, Hx, Sx, 0.125f,
            NHx, (long long)Sx*Hx, 64, (long long)Sx*Hx, 64,
            (long long)NHx*Sx*Sx, (long long)Sx*Sx);

        softmax_k<<<dim3(Sx, Bx*NHx), 256>>>();

        dim3 gpv(1, Sx/BM, Bx*NHx);
        gemm_k<0,0,0,0,1><<<gpv,256>>>(ps, pv, nullptr, pa,
            Sx, HDx, Sx, Sx, Hx, Hx, 1.f,
            NHx, (long long)NHx*Sx*Sx, (long long)Sx*Sx,
            (long long)Sx*Hx, 64, (long long)Sx*Hx, 64);

        gemm_k<0,0,1><<<gp,256>>>(pa, Wo + (size_t)l*Hx*Hx, bo + l*Hx, px,
            Ntok, Hx, Hx, Hx, Hx, Hx, 1.f, 0, 0,0,0,0,0,0);

        // ---- MoE ----
        ln_k<<<Ntok, 256>>>(px, ln2w + l*Hx, ln2b + l*Hx, ph);
        router_k<<<Ntok/8, 256>>>(ph, Wr + (size_t)l*Hx*Ex, br + l*Ex);
        zero_k<<<1, 32>>>();
        count_k<<<NSLOT/256, 256>>>();
        scan_k<<<1, 1>>>();
        scatter_k<<<NSLOT/256, 256>>>();
        moe1_k<<<dim3(Fx/BN, Ntok/BM, Ex), 256>>>(ph, W1 + (size_t)l*Ex*Hx*Fx, b1 + (size_t)l*Ex*Fx);
        moe2_k<<<dim3(Hx/BN, Ntok/BM, Ex), 256>>>(W2 + (size_t)l*Ex*Fx*Hx, b2 + (size_t)l*Ex*Hx);
        combine_k<<<(Ntok*Hx + 255)/256, 256>>>();
    }

    ln_k<<<Ntok, 256>>>(px, lnfw, lnfb, ph);
    split_k<<<(Ntok*Hx)/256, 256>>>(ph, phh, phl, (size_t)Ntok*Hx);
    lmhead_hmma_k<<<dim3(Ntok/128, (Vx + 127)/128), 256>>>(out);
}

// round 12
// speedup vs baseline: 1.5088x; 1.2352x over previous
#include <cuda_runtime.h>
#include <cuda_bf16.h>
#include <math.h>
#include <stdint.h>

#define Lx   2
#define Bx   2
#define Sx   1024
#define Hx   768
#define NHx  12
#define HDx  64
#define Ex   8
#define KKx  2
#define Fx   3072
#define Vx   50257
#define Ntok (Bx*Sx)          /* 2048 */
#define NSLOT (Ntok*KKx)      /* 4096 */
#define EPSx 1e-5f

#define BM 128
#define BN 128
#define BKK 8

// ---------------- scratch (static __device__ arrays; allocation-free) -------
__device__ float g_x[Ntok*Hx];
__device__ float g_h[Ntok*Hx];
__device__ float g_q[Ntok*Hx];
__device__ float g_k[Ntok*Hx];
__device__ float g_v[Ntok*Hx];
__device__ float g_att[Ntok*Hx];
__device__ float g_scores[(size_t)Bx*NHx*Sx*Sx];   // ~100 MB
__device__ float g_oe[(size_t)NSLOT*Hx];
__device__ float g_tp[NSLOT];
__device__ int   g_ti[NSLOT];
__device__ int   g_cnt[Ex];
__device__ int   g_off[Ex+1];
__device__ int   g_fill[Ex];
__device__ int   g_slot_tok[NSLOT];
__device__ int   g_tok2slot[NSLOT];
// bf16-split operands for HMMA kernels
__device__ __nv_bfloat16 g_h_hi[Ntok*Hx];
__device__ __nv_bfloat16 g_h_lo[Ntok*Hx];
__device__ __nv_bfloat16 g_emb_hi[(size_t)Vx*Hx];
__device__ __nv_bfloat16 g_emb_lo[(size_t)Vx*Hx];
__device__ __nv_bfloat16 g_act_hi[(size_t)NSLOT*Fx];
__device__ __nv_bfloat16 g_act_lo[(size_t)NSLOT*Fx];
// transposed ([N][K]) bf16-split MoE weights
__device__ __nv_bfloat16 g_w1t_hi[(size_t)Lx*Ex*Fx*Hx];
__device__ __nv_bfloat16 g_w1t_lo[(size_t)Lx*Ex*Fx*Hx];
__device__ __nv_bfloat16 g_w2t_hi[(size_t)Lx*Ex*Hx*Fx];
__device__ __nv_bfloat16 g_w2t_lo[(size_t)Lx*Ex*Hx*Fx];

__device__ __forceinline__ float gelu_f(float x) {
    return 0.5f * x * (1.0f + erff(x * 0.70710678118654752440f));
}

__device__ __forceinline__ uint32_t smem_u32(const void* p) {
    uint32_t a;
    asm("{ .reg .u64 t; cvta.to.shared.u64 t, %1; cvt.u32.u64 %0, t; }" : "=r"(a) : "l"(p));
    return a;
}
__device__ __forceinline__ void ldmx4(uint32_t* r, uint32_t addr) {
    asm volatile("ldmatrix.sync.aligned.m8n8.x4.shared.b16 {%0,%1,%2,%3}, [%4];"
        : "=r"(r[0]), "=r"(r[1]), "=r"(r[2]), "=r"(r[3]) : "r"(addr));
}
__device__ __forceinline__ void mma16816(float* d, const uint32_t* a, uint32_t b0, uint32_t b1) {
    asm volatile("mma.sync.aligned.m16n8k16.row.col.f32.bf16.bf16.f32 "
        "{%0,%1,%2,%3}, {%4,%5,%6,%7}, {%8,%9}, {%0,%1,%2,%3};"
        : "+f"(d[0]), "+f"(d[1]), "+f"(d[2]), "+f"(d[3])
        : "r"(a[0]), "r"(a[1]), "r"(a[2]), "r"(a[3]), "r"(b0), "r"(b1));
}

// ---------------- embedding gather ------------------------------------------
__global__ void embed_k(const int* __restrict__ ids, const float* __restrict__ emb)
{
    int i = blockIdx.x * 256 + threadIdx.x;
    if (i >= Ntok*Hx) return;
    int n = i / Hx, hh = i % Hx;
    g_x[i] = emb[(size_t)ids[n]*Hx + hh];
}

// ---------------- bf16 split: x = hi + lo ------------------------------------
__global__ void split_k(const float* __restrict__ X, __nv_bfloat16* __restrict__ hi,
                        __nv_bfloat16* __restrict__ lo, size_t n)
{
    size_t i = (size_t)blockIdx.x * 256 + threadIdx.x;
    if (i >= n) return;
    float v = X[i];
    __nv_bfloat16 h = __float2bfloat16_rn(v);
    hi[i] = h;
    lo[i] = __float2bfloat16_rn(v - __bfloat162float(h));
}

// ---------------- transpose + split: W[K][N] fp32 -> Wt[N][K] bf16 hi/lo ----
__global__ __launch_bounds__(256)
void tsplit_k(const float* __restrict__ W, __nv_bfloat16* __restrict__ hi,
              __nv_bfloat16* __restrict__ lo, int K, int N)
{
    __shared__ float t[32][33];
    int z = blockIdx.z;
    const float* Wb = W + (size_t)z*K*N;
    __nv_bfloat16* hb = hi + (size_t)z*N*K;
    __nv_bfloat16* lb = lo + (size_t)z*N*K;
    int tx = threadIdx.x & 31, ty = threadIdx.x >> 5;   // 32 x 8
    int k0 = blockIdx.y * 32, n0 = blockIdx.x * 32;
    #pragma unroll
    for (int r = 0; r < 4; r++)
        t[ty + r*8][tx] = Wb[(size_t)(k0 + ty + r*8)*N + n0 + tx];
    __syncthreads();
    #pragma unroll
    for (int r = 0; r < 4; r++) {
        int n = n0 + ty + r*8, k = k0 + tx;
        float v = t[tx][ty + r*8];
        __nv_bfloat16 h = __float2bfloat16_rn(v);
        hb[(size_t)n*K + k] = h;
        lb[(size_t)n*K + k] = __float2bfloat16_rn(v - __bfloat162float(h));
    }
}

// ---------------- layernorm (one block per token) ---------------------------
__global__ __launch_bounds__(256)
void ln_k(const float* __restrict__ X, const float* __restrict__ w,
          const float* __restrict__ b, float* __restrict__ Y)
{
    int n = blockIdx.x;
    __shared__ float sx[Hx];
    __shared__ float red[256];
    const float* xr = X + (size_t)n*Hx;
    int t = threadIdx.x;
    float s = 0.f;
    for (int i = t; i < Hx; i += 256) { float v = xr[i]; sx[i] = v; s += v; }
    red[t] = s; __syncthreads();
    for (int o = 128; o > 0; o >>= 1) { if (t < o) red[t] += red[t+o]; __syncthreads(); }
    float mean = red[0] * (1.0f/Hx);
    __syncthreads();
    float s2 = 0.f;
    for (int i = t; i < Hx; i += 256) { float d = sx[i]-mean; s2 += d*d; }
    __syncthreads();
    red[t] = s2; __syncthreads();
    for (int o = 128; o > 0; o >>= 1) { if (t < o) red[t] += red[t+o]; __syncthreads(); }
    float inv = rsqrtf(red[0] * (1.0f/Hx) + EPSx);
    for (int i = t; i < Hx; i += 256)
        Y[(size_t)n*Hx + i] = (sx[i]-mean)*inv*w[i] + b[i];
}

// ---------------- generic tiled SGEMM (attention + Wo) -----------------------
template<int TB, int ACT, int ADD, int CSKIP = 0, int KCLAMP = 0>
__global__ __launch_bounds__(256)
void gemm_k(const float* __restrict__ A, const float* __restrict__ B,
            const float* __restrict__ bias, float* __restrict__ C,
            int M, int N, int Kd, int lda, int ldb, int ldc, float alpha,
            int zdiv, long long sAb, long long sAh, long long sBb, long long sBh,
            long long sCb, long long sCh)
{
    const int m0 = blockIdx.y * BM;
    const int n0 = blockIdx.x * BN;
    if (CSKIP && n0 > m0) return;
    if (KCLAMP && m0 + BM < Kd) Kd = m0 + BM;
    if (zdiv > 0) {
        int z = blockIdx.z;
        int zb = z / zdiv, zh = z % zdiv;
        A += (long long)zb*sAb + (long long)zh*sAh;
        B += (long long)zb*sBb + (long long)zh*sBh;
        C += (long long)zb*sCb + (long long)zh*sCh;
    }
    __shared__ __align__(16) float As[BKK][BM];
    __shared__ __align__(16) float Bs[BKK][BN];
    const int tid = threadIdx.x;
    const int arow = tid >> 1, acol = (tid & 1) * 4;
    const int tr = (tid >> 4) << 3;
    const int tc = (tid & 15) << 3;

    float acc[8][8];
    #pragma unroll
    for (int i = 0; i < 8; i++)
        #pragma unroll
        for (int j = 0; j < 8; j++) acc[i][j] = 0.f;

    for (int k0 = 0; k0 < Kd; k0 += BKK) {
        {
            int gm = m0 + arow;
            float4 av = make_float4(0.f,0.f,0.f,0.f);
            if (gm < M) av = *(const float4*)&A[(size_t)gm*lda + k0 + acol];
            As[acol+0][arow] = av.x; As[acol+1][arow] = av.y;
            As[acol+2][arow] = av.z; As[acol+3][arow] = av.w;
        }
        if (TB) {
            int bn = tid >> 1, bk = (tid & 1) * 4;
            int gn = n0 + bn;
            float4 bv = make_float4(0.f,0.f,0.f,0.f);
            if (gn < N) bv = *(const float4*)&B[(size_t)gn*ldb + k0 + bk];
            Bs[bk+0][bn] = bv.x; Bs[bk+1][bn] = bv.y;
            Bs[bk+2][bn] = bv.z; Bs[bk+3][bn] = bv.w;
        } else {
            int bk = tid >> 5, bn = (tid & 31) * 4;
            int gn = n0 + bn;
            float4 bv = make_float4(0.f,0.f,0.f,0.f);
            if (gn < N) bv = *(const float4*)&B[(size_t)(k0+bk)*ldb + gn];
            *(float4*)&Bs[bk][bn] = bv;
        }
        __syncthreads();
        #pragma unroll
        for (int kk = 0; kk < BKK; kk++) {
            float a[8], b[8];
            #pragma unroll
            for (int i = 0; i < 8; i++) a[i] = As[kk][tr+i];
            #pragma unroll
            for (int j = 0; j < 8; j++) b[j] = Bs[kk][tc+j];
            #pragma unroll
            for (int i = 0; i < 8; i++)
                #pragma unroll
                for (int j = 0; j < 8; j++)
                    acc[i][j] = fmaf(a[i], b[j], acc[i][j]);
        }
        __syncthreads();
    }
    #pragma unroll
    for (int i = 0; i < 8; i++) {
        int gm = m0 + tr + i;
        if (gm >= M) continue;
        #pragma unroll
        for (int j = 0; j < 8; j++) {
            int gn = n0 + tc + j;
            if (gn >= N) continue;
            float v = acc[i][j] * alpha;
            if (bias) v += bias[gn];
            if (ACT == 1) v = gelu_f(v);
            size_t idx = (size_t)gm*ldc + gn;
            if (ADD) C[idx] += v; else C[idx] = v;
        }
    }
}

// ---------------- fused QKV projection (z selects q/k/v) ----------------------
__global__ __launch_bounds__(256)
void qkv_k(const float* __restrict__ Hin,
           const float* __restrict__ Wq, const float* __restrict__ Wk2, const float* __restrict__ Wv,
           const float* __restrict__ bq, const float* __restrict__ bk2, const float* __restrict__ bv,
           float* __restrict__ Q, float* __restrict__ Ko, float* __restrict__ V)
{
    int z = blockIdx.z;
    const float* B    = (z == 0) ? Wq : (z == 1) ? Wk2 : Wv;
    const float* bias = (z == 0) ? bq : (z == 1) ? bk2 : bv;
    float* C          = (z == 0) ? Q  : (z == 1) ? Ko  : V;
    const int m0 = blockIdx.y * BM;
    const int n0 = blockIdx.x * BN;
    __shared__ __align__(16) float As[BKK][BM];
    __shared__ __align__(16) float Bs[BKK][BN];
    const int tid = threadIdx.x;
    const int arow = tid >> 1, acol = (tid & 1) * 4;
    const int bk = tid >> 5, bn = (tid & 31) * 4;
    const int tr = (tid >> 4) << 3;
    const int tc = (tid & 15) << 3;

    float acc[8][8];
    #pragma unroll
    for (int i = 0; i < 8; i++)
        #pragma unroll
        for (int j = 0; j < 8; j++) acc[i][j] = 0.f;

    for (int k0 = 0; k0 < Hx; k0 += BKK) {
        float4 av = *(const float4*)&Hin[(size_t)(m0+arow)*Hx + k0 + acol];
        As[acol+0][arow] = av.x; As[acol+1][arow] = av.y;
        As[acol+2][arow] = av.z; As[acol+3][arow] = av.w;
        *(float4*)&Bs[bk][bn] = *(const float4*)&B[(size_t)(k0+bk)*Hx + n0 + bn];
        __syncthreads();
        #pragma unroll
        for (int kk = 0; kk < BKK; kk++) {
            float a[8], b[8];
            #pragma unroll
            for (int i = 0; i < 8; i++) a[i] = As[kk][tr+i];
            #pragma unroll
            for (int j = 0; j < 8; j++) b[j] = Bs[kk][tc+j];
            #pragma unroll
            for (int i = 0; i < 8; i++)
                #pragma unroll
                for (int j = 0; j < 8; j++)
                    acc[i][j] = fmaf(a[i], b[j], acc[i][j]);
        }
        __syncthreads();
    }
    #pragma unroll
    for (int i = 0; i < 8; i++)
        #pragma unroll
        for (int j = 0; j < 8; j++)
            C[(size_t)(m0+tr+i)*Hx + n0+tc+j] = acc[i][j] + bias[n0+tc+j];
}

// ---------------- bf16-split HMMA GEMM cores --------------------------------
#define LM_LDS 40                     /* 32 + 8 pad; conflict-free for ldmatrix */

// C[2048, 50257] = h @ emb^T  (validated R8)
__global__ __launch_bounds__(256)
void lmhead_hmma_k(float* __restrict__ C)
{
    __shared__ __nv_bfloat16 sAhi[128][LM_LDS], sAlo[128][LM_LDS];
    __shared__ __nv_bfloat16 sBhi[128][LM_LDS], sBlo[128][LM_LDS];
    const int tid = threadIdx.x;
    const int wid = tid >> 5, lane = tid & 31;
    const int m0 = blockIdx.x * 128;
    const int n0 = blockIdx.y * 128;
    const int wm = (wid & 3) * 32;
    const int wn = (wid >> 2) * 64;

    float acc[2][8][4];
    #pragma unroll
    for (int mt = 0; mt < 2; mt++)
        #pragma unroll
        for (int nt = 0; nt < 8; nt++)
            #pragma unroll
            for (int r = 0; r < 4; r++) acc[mt][nt][r] = 0.f;

    const int lrow = tid >> 1;
    const int lcol = (tid & 1) * 16;
    const int a_r = lane & 15, a_c = (lane >> 4) * 8;
    const int b_r = (lane & 7) + ((lane >> 4) & 1) * 8;
    const int b_c = ((lane >> 3) & 1) * 8;

    for (int kc = 0; kc < Hx/32; kc++) {
        const int kg = kc * 32 + lcol;
        {
            const uint4* s = (const uint4*)&g_h_hi[(size_t)(m0+lrow)*Hx + kg];
            *(uint4*)&sAhi[lrow][lcol]   = s[0];
            *(uint4*)&sAhi[lrow][lcol+8] = s[1];
            s = (const uint4*)&g_h_lo[(size_t)(m0+lrow)*Hx + kg];
            *(uint4*)&sAlo[lrow][lcol]   = s[0];
            *(uint4*)&sAlo[lrow][lcol+8] = s[1];
        }
        {
            int n = n0 + lrow;
            uint4 h0 = make_uint4(0,0,0,0), h1 = h0, l0 = h0, l1 = h0;
            if (n < Vx) {
                const uint4* s = (const uint4*)&g_emb_hi[(size_t)n*Hx + kg];
                h0 = s[0]; h1 = s[1];
                s = (const uint4*)&g_emb_lo[(size_t)n*Hx + kg];
                l0 = s[0]; l1 = s[1];
            }
            *(uint4*)&sBhi[lrow][lcol]   = h0;
            *(uint4*)&sBhi[lrow][lcol+8] = h1;
            *(uint4*)&sBlo[lrow][lcol]   = l0;
            *(uint4*)&sBlo[lrow][lcol+8] = l1;
        }
        __syncthreads();
        #pragma unroll
        for (int pass = 0; pass < 3; pass++) {
            const __nv_bfloat16 (*pA)[LM_LDS] = (pass == 2) ? sAlo : sAhi;
            const __nv_bfloat16 (*pB)[LM_LDS] = (pass == 1) ? sBlo : sBhi;
            #pragma unroll
            for (int ks = 0; ks < 2; ks++) {
                const int k0 = ks * 16;
                uint32_t af[2][4];
                #pragma unroll
                for (int mt = 0; mt < 2; mt++)
                    ldmx4(af[mt], smem_u32(&pA[wm + mt*16 + a_r][k0 + a_c]));
                uint32_t bf[4][4];
                #pragma unroll
                for (int bq = 0; bq < 4; bq++)
                    ldmx4(bf[bq], smem_u32(&pB[wn + bq*16 + b_r][k0 + b_c]));
                #pragma unroll
                for (int mt = 0; mt < 2; mt++)
                    #pragma unroll
                    for (int nt = 0; nt < 8; nt++)
                        mma16816(acc[mt][nt], af[mt],
                                 bf[nt >> 1][(nt & 1)*2], bf[nt >> 1][(nt & 1)*2 + 1]);
            }
        }
        __syncthreads();
    }

    const int er = lane >> 2, ec = (lane & 3) * 2;
    #pragma unroll
    for (int mt = 0; mt < 2; mt++) {
        #pragma unroll
        for (int nt = 0; nt < 8; nt++) {
            int row = m0 + wm + mt*16 + er;
            int col = n0 + wn + nt*8 + ec;
            if (col < Vx) {
                C[(size_t)row*Vx + col] = acc[mt][nt][0];
                C[(size_t)(row+8)*Vx + col] = acc[mt][nt][2];
            }
            if (col + 1 < Vx) {
                C[(size_t)row*Vx + col + 1] = acc[mt][nt][1];
                C[(size_t)(row+8)*Vx + col + 1] = acc[mt][nt][3];
            }
        }
    }
}

// MoE stage 1: act = gelu(gather(h) @ W1t^T + b1); writes bf16 hi/lo
__global__ __launch_bounds__(256)
void moe1_hmma_k(const float* __restrict__ b1l, int layer)
{
    __shared__ __nv_bfloat16 sAhi[128][LM_LDS], sAlo[128][LM_LDS];
    __shared__ __nv_bfloat16 sBhi[128][LM_LDS], sBlo[128][LM_LDS];
    const int e = blockIdx.z;
    const int base = g_off[e];
    const int cnt  = g_off[e+1] - base;
    const int m0 = blockIdx.x * 128;
    if (m0 >= cnt) return;
    const int n0 = blockIdx.y * 128;
    const size_t wb = ((size_t)layer*Ex + e)*(size_t)Fx*Hx;
    const float* bias = b1l + (size_t)e*Fx;

    const int tid = threadIdx.x;
    const int wid = tid >> 5, lane = tid & 31;
    const int wm = (wid & 3) * 32;
    const int wn = (wid >> 2) * 64;

    float acc[2][8][4];
    #pragma unroll
    for (int mt = 0; mt < 2; mt++)
        #pragma unroll
        for (int nt = 0; nt < 8; nt++)
            #pragma unroll
            for (int r = 0; r < 4; r++) acc[mt][nt][r] = 0.f;

    const int lrow = tid >> 1;
    const int lcol = (tid & 1) * 16;
    const int a_r = lane & 15, a_c = (lane >> 4) * 8;
    const int b_r = (lane & 7) + ((lane >> 4) & 1) * 8;
    const int b_c = ((lane >> 3) & 1) * 8;

    int tok = (m0 + lrow < cnt) ? g_slot_tok[base + m0 + lrow] : -1;

    for (int kc = 0; kc < Hx/32; kc++) {
        const int kg = kc * 32 + lcol;
        {
            uint4 h0 = make_uint4(0,0,0,0), l0 = h0;
            uint4 h1 = h0, l1 = h0;
            if (tok >= 0) {
                const uint4* s = (const uint4*)&g_h_hi[(size_t)tok*Hx + kg];
                h0 = s[0]; h1 = s[1];
                s = (const uint4*)&g_h_lo[(size_t)tok*Hx + kg];
                l0 = s[0]; l1 = s[1];
            }
            *(uint4*)&sAhi[lrow][lcol]   = h0;
            *(uint4*)&sAhi[lrow][lcol+8] = h1;
            *(uint4*)&sAlo[lrow][lcol]   = l0;
            *(uint4*)&sAlo[lrow][lcol+8] = l1;
        }
        {
            size_t gidx = wb + (size_t)(n0 + lrow)*Hx + kg;
            const uint4* s = (const uint4*)&g_w1t_hi[gidx];
            *(uint4*)&sBhi[lrow][lcol]   = s[0];
            *(uint4*)&sBhi[lrow][lcol+8] = s[1];
            s = (const uint4*)&g_w1t_lo[gidx];
            *(uint4*)&sBlo[lrow][lcol]   = s[0];
            *(uint4*)&sBlo[lrow][lcol+8] = s[1];
        }
        __syncthreads();
        #pragma unroll
        for (int pass = 0; pass < 3; pass++) {
            const __nv_bfloat16 (*pA)[LM_LDS] = (pass == 2) ? sAlo : sAhi;
            const __nv_bfloat16 (*pB)[LM_LDS] = (pass == 1) ? sBlo : sBhi;
            #pragma unroll
            for (int ks = 0; ks < 2; ks++) {
                const int k0 = ks * 16;
                uint32_t af[2][4];
                #pragma unroll
                for (int mt = 0; mt < 2; mt++)
                    ldmx4(af[mt], smem_u32(&pA[wm + mt*16 + a_r][k0 + a_c]));
                uint32_t bf[4][4];
                #pragma unroll
                for (int bq = 0; bq < 4; bq++)
                    ldmx4(bf[bq], smem_u32(&pB[wn + bq*16 + b_r][k0 + b_c]));
                #pragma unroll
                for (int mt = 0; mt < 2; mt++)
                    #pragma unroll
                    for (int nt = 0; nt < 8; nt++)
                        mma16816(acc[mt][nt], af[mt],
                                 bf[nt >> 1][(nt & 1)*2], bf[nt >> 1][(nt & 1)*2 + 1]);
            }
        }
        __syncthreads();
    }

    const int er = lane >> 2, ec = (lane & 3) * 2;
    #pragma unroll
    for (int mt = 0; mt < 2; mt++) {
        #pragma unroll
        for (int nt = 0; nt < 8; nt++) {
            int rl = wm + mt*16 + er;
            int col = n0 + wn + nt*8 + ec;
            #pragma unroll
            for (int rr = 0; rr < 2; rr++) {
                int row = m0 + rl + rr*8;
                if (row >= cnt) continue;
                #pragma unroll
                for (int cc = 0; cc < 2; cc++) {
                    float g = gelu_f(acc[mt][nt][rr*2 + cc] + bias[col + cc]);
                    __nv_bfloat16 h = __float2bfloat16_rn(g);
                    size_t idx = (size_t)(base + row)*Fx + col + cc;
                    g_act_hi[idx] = h;
                    g_act_lo[idx] = __float2bfloat16_rn(g - __bfloat162float(h));
                }
            }
        }
    }
}

// MoE stage 2: oe = act @ W2t^T + b2 (fp32 out)
__global__ __launch_bounds__(256)
void moe2_hmma_k(const float* __restrict__ b2l, int layer)
{
    __shared__ __nv_bfloat16 sAhi[128][LM_LDS], sAlo[128][LM_LDS];
    __shared__ __nv_bfloat16 sBhi[128][LM_LDS], sBlo[128][LM_LDS];
    const int e = blockIdx.z;
    const int base = g_off[e];
    const int cnt  = g_off[e+1] - base;
    const int m0 = blockIdx.x * 128;
    if (m0 >= cnt) return;
    const int n0 = blockIdx.y * 128;
    const size_t wb = ((size_t)layer*Ex + e)*(size_t)Fx*Hx;
    const float* bias = b2l + (size_t)e*Hx;

    const int tid = threadIdx.x;
    const int wid = tid >> 5, lane = tid & 31;
    const int wm = (wid & 3) * 32;
    const int wn = (wid >> 2) * 64;

    float acc[2][8][4];
    #pragma unroll
    for (int mt = 0; mt < 2; mt++)
        #pragma unroll
        for (int nt = 0; nt < 8; nt++)
            #pragma unroll
            for (int r = 0; r < 4; r++) acc[mt][nt][r] = 0.f;

    const int lrow = tid >> 1;
    const int lcol = (tid & 1) * 16;
    const int a_r = lane & 15, a_c = (lane >> 4) * 8;
    const int b_r = (lane & 7) + ((lane >> 4) & 1) * 8;
    const int b_c = ((lane >> 3) & 1) * 8;

    const bool arow_ok = (m0 + lrow < cnt);
    const size_t aslot = (size_t)(base + m0 + lrow)*Fx;

    for (int kc = 0; kc < Fx/32; kc++) {
        const int kg = kc * 32 + lcol;
        {
            uint4 h0 = make_uint4(0,0,0,0), h1 = h0, l0 = h0, l1 = h0;
            if (arow_ok) {
                const uint4* s = (const uint4*)&g_act_hi[aslot + kg];
                h0 = s[0]; h1 = s[1];
                s = (const uint4*)&g_act_lo[aslot + kg];
                l0 = s[0]; l1 = s[1];
            }
            *(uint4*)&sAhi[lrow][lcol]   = h0;
            *(uint4*)&sAhi[lrow][lcol+8] = h1;
            *(uint4*)&sAlo[lrow][lcol]   = l0;
            *(uint4*)&sAlo[lrow][lcol+8] = l1;
        }
        {
            size_t gidx = wb + (size_t)(n0 + lrow)*Fx + kg;
            const uint4* s = (const uint4*)&g_w2t_hi[gidx];
            *(uint4*)&sBhi[lrow][lcol]   = s[0];
            *(uint4*)&sBhi[lrow][lcol+8] = s[1];
            s = (const uint4*)&g_w2t_lo[gidx];
            *(uint4*)&sBlo[lrow][lcol]   = s[0];
            *(uint4*)&sBlo[lrow][lcol+8] = s[1];
        }
        __syncthreads();
        #pragma unroll
        for (int pass = 0; pass < 3; pass++) {
            const __nv_bfloat16 (*pA)[LM_LDS] = (pass == 2) ? sAlo : sAhi;
            const __nv_bfloat16 (*pB)[LM_LDS] = (pass == 1) ? sBlo : sBhi;
            #pragma unroll
            for (int ks = 0; ks < 2; ks++) {
                const int k0 = ks * 16;
                uint32_t af[2][4];
                #pragma unroll
                for (int mt = 0; mt < 2; mt++)
                    ldmx4(af[mt], smem_u32(&pA[wm + mt*16 + a_r][k0 + a_c]));
                uint32_t bf[4][4];
                #pragma unroll
                for (int bq = 0; bq < 4; bq++)
                    ldmx4(bf[bq], smem_u32(&pB[wn + bq*16 + b_r][k0 + b_c]));
                #pragma unroll
                for (int mt = 0; mt < 2; mt++)
                    #pragma unroll
                    for (int nt = 0; nt < 8; nt++)
                        mma16816(acc[mt][nt], af[mt],
                                 bf[nt >> 1][(nt & 1)*2], bf[nt >> 1][(nt & 1)*2 + 1]);
            }
        }
        __syncthreads();
    }

    const int er = lane >> 2, ec = (lane & 3) * 2;
    #pragma unroll
    for (int mt = 0; mt < 2; mt++) {
        #pragma unroll
        for (int nt = 0; nt < 8; nt++) {
            int rl = wm + mt*16 + er;
            int col = n0 + wn + nt*8 + ec;
            #pragma unroll
            for (int rr = 0; rr < 2; rr++) {
                int row = m0 + rl + rr*8;
                if (row >= cnt) continue;
                #pragma unroll
                for (int cc = 0; cc < 2; cc++)
                    g_oe[(size_t)(base + row)*Hx + col + cc] =
                        acc[mt][nt][rr*2 + cc] + bias[col + cc];
            }
        }
    }
}

// ---------------- RoPE -------------------------------------------------------
__global__ void rope_k()
{
    int i = blockIdx.x * 256 + threadIdx.x;
    if (i >= Ntok*NHx*32) return;
    int d = i & 31;
    int rest = i >> 5;
    int head = rest % NHx;
    int n = rest / NHx;
    int s = n & (Sx-1);
    double inv = exp(-9.210340371976184 * (double)d / 32.0);
    double ang = (double)s * inv;
    float c = (float)cos(ang);
    float sn = (float)sin(ang);
    size_t base = (size_t)n*Hx + head*64 + d;
    float a = g_q[base], b2 = g_q[base+32];
    g_q[base]    = a*c - b2*sn;
    g_q[base+32] = b2*c + a*sn;
    a = g_k[base]; b2 = g_k[base+32];
    g_k[base]    = a*c - b2*sn;
    g_k[base+32] = b2*c + a*sn;
}

// ---------------- causal-masked softmax --------------------------------------
__global__ __launch_bounds__(256)
void softmax_k()
{
    int qi = blockIdx.x;
    int z  = blockIdx.y;
    float* row = g_scores + (size_t)z*Sx*Sx + (size_t)qi*Sx;
    __shared__ float red[256];
    int t = threadIdx.x;
    float lv[4];
    float mx = -3.0e38f;
    #pragma unroll
    for (int u = 0; u < 4; u++) {
        int j = t + u*256;
        float v = (j > qi) ? -INFINITY : row[j];
        lv[u] = v; mx = fmaxf(mx, v);
    }
    red[t] = mx; __syncthreads();
    for (int o = 128; o > 0; o >>= 1) { if (t < o) red[t] = fmaxf(red[t], red[t+o]); __syncthreads(); }
    mx = red[0]; __syncthreads();
    float sum = 0.f;
    #pragma unroll
    for (int u = 0; u < 4; u++) { lv[u] = expf(lv[u]-mx); sum += lv[u]; }
    red[t] = sum; __syncthreads();
    for (int o = 128; o > 0; o >>= 1) { if (t < o) red[t] += red[t+o]; __syncthreads(); }
    float inv = 1.0f / red[0];
    #pragma unroll
    for (int u = 0; u < 4; u++) row[t + u*256] = lv[u]*inv;
}

// ---------------- MoE router -------------------------------------------------
__global__ void router_k(const float* __restrict__ Hin, const float* __restrict__ Wr,
                         const float* __restrict__ br)
{
    int warp = threadIdx.x >> 5, lane = threadIdx.x & 31;
    int n = blockIdx.x * 8 + warp;
    if (n >= Ntok) return;
    const float* hr = Hin + (size_t)n*Hx;
    float p[Ex];
    #pragma unroll
    for (int e = 0; e < Ex; e++) {
        float s = 0.f;
        for (int i = lane; i < Hx; i += 32) s = fmaf(hr[i], Wr[i*Ex + e], s);
        #pragma unroll
        for (int o = 16; o > 0; o >>= 1) s += __shfl_xor_sync(0xffffffffu, s, o);
        p[e] = s + br[e];
    }
    if (lane == 0) {
        float m = p[0];
        #pragma unroll
        for (int e = 1; e < Ex; e++) m = fmaxf(m, p[e]);
        float sum = 0.f;
        #pragma unroll
        for (int e = 0; e < Ex; e++) { p[e] = expf(p[e]-m); sum += p[e]; }
        float is = 1.0f/sum;
        #pragma unroll
        for (int e = 0; e < Ex; e++) p[e] *= is;
        int i1 = 0;
        #pragma unroll
        for (int e = 1; e < Ex; e++) if (p[e] > p[i1]) i1 = e;
        int i2 = (i1 == 0) ? 1 : 0;
        #pragma unroll
        for (int e = 0; e < Ex; e++) { if (e == i1 || e == i2) continue; if (p[e] > p[i2]) i2 = e; }
        float t1 = p[i1], t2 = p[i2];
        float isum = 1.0f / (t1 + t2 + 1e-9f);
        g_ti[n*2] = i1;  g_ti[n*2+1] = i2;
        g_tp[n*2] = t1*isum; g_tp[n*2+1] = t2*isum;
    }
}

__global__ void zero_k() { int t = threadIdx.x; if (t < Ex) { g_cnt[t] = 0; g_fill[t] = 0; } }
__global__ void count_k() { int i = blockIdx.x*256+threadIdx.x; if (i < NSLOT) atomicAdd(&g_cnt[g_ti[i]], 1); }
__global__ void scan_k()  { g_off[0] = 0; for (int e = 0; e < Ex; e++) g_off[e+1] = g_off[e] + g_cnt[e]; }
__global__ void scatter_k()
{
    int i = blockIdx.x*256+threadIdx.x;
    if (i >= NSLOT) return;
    int e = g_ti[i];
    int pos = atomicAdd(&g_fill[e], 1);
    int slot = g_off[e] + pos;
    g_slot_tok[slot] = i >> 1;
    g_tok2slot[i] = slot;
}

// ---------------- combine ----------------------------------------------------
__global__ void combine_k()
{
    int i = blockIdx.x*256+threadIdx.x;
    if (i >= Ntok*Hx) return;
    int n = i / Hx, hh = i % Hx;
    int s0 = g_tok2slot[n*2], s1 = g_tok2slot[n*2+1];
    g_x[i] += g_tp[n*2]  * g_oe[(size_t)s0*Hx + hh]
            + g_tp[n*2+1]* g_oe[(size_t)s1*Hx + hh];
}

// ---------------- host orchestration ----------------------------------------
extern "C" void kernel_launch(void* const* d_in, const int* in_sizes, int n_in,
                              void* d_out, int out_size)
{
    const int*   ids  = (const int*)  d_in[0];
    const float* emb  = (const float*)d_in[1];
    const float* ln1w = (const float*)d_in[2];
    const float* ln1b = (const float*)d_in[3];
    const float* ln2w = (const float*)d_in[4];
    const float* ln2b = (const float*)d_in[5];
    const float* lnfw = (const float*)d_in[6];
    const float* lnfb = (const float*)d_in[7];
    const float* Wq   = (const float*)d_in[8];
    const float* bq   = (const float*)d_in[9];
    const float* Wk   = (const float*)d_in[10];
    const float* bkb  = (const float*)d_in[11];
    const float* Wv   = (const float*)d_in[12];
    const float* bv   = (const float*)d_in[13];
    const float* Wo   = (const float*)d_in[14];
    const float* bo   = (const float*)d_in[15];
    const float* Wr   = (const float*)d_in[16];
    const float* br   = (const float*)d_in[17];
    const float* W1   = (const float*)d_in[18];
    const float* b1   = (const float*)d_in[19];
    const float* W2   = (const float*)d_in[20];
    const float* b2   = (const float*)d_in[21];
    float* out = (float*)d_out;

    float *px, *ph, *pq, *pk, *pv, *pa, *ps;
    cudaGetSymbolAddress((void**)&px, g_x);
    cudaGetSymbolAddress((void**)&ph, g_h);
    cudaGetSymbolAddress((void**)&pq, g_q);
    cudaGetSymbolAddress((void**)&pk, g_k);
    cudaGetSymbolAddress((void**)&pv, g_v);
    cudaGetSymbolAddress((void**)&pa, g_att);
    cudaGetSymbolAddress((void**)&ps, g_scores);
    __nv_bfloat16 *phh, *phl, *peh, *pel, *pw1h, *pw1l, *pw2h, *pw2l;
    cudaGetSymbolAddress((void**)&phh, g_h_hi);
    cudaGetSymbolAddress((void**)&phl, g_h_lo);
    cudaGetSymbolAddress((void**)&peh, g_emb_hi);
    cudaGetSymbolAddress((void**)&pel, g_emb_lo);
    cudaGetSymbolAddress((void**)&pw1h, g_w1t_hi);
    cudaGetSymbolAddress((void**)&pw1l, g_w1t_lo);
    cudaGetSymbolAddress((void**)&pw2h, g_w2t_hi);
    cudaGetSymbolAddress((void**)&pw2l, g_w2t_lo);

    embed_k<<<(Ntok*Hx + 255)/256, 256>>>(ids, emb);
    split_k<<<(int)(((size_t)Vx*Hx + 255)/256), 256>>>(emb, peh, pel, (size_t)Vx*Hx);
    // transpose-split MoE weights: W[K][N] -> Wt[N][K] bf16 hi/lo
    tsplit_k<<<dim3(Fx/32, Hx/32, Lx*Ex), 256>>>(W1, pw1h, pw1l, Hx, Fx);
    tsplit_k<<<dim3(Hx/32, Fx/32, Lx*Ex), 256>>>(W2, pw2h, pw2l, Fx, Hx);

    for (int l = 0; l < Lx; l++) {
        ln_k<<<Ntok, 256>>>(px, ln1w + l*Hx, ln1b + l*Hx, ph);

        qkv_k<<<dim3(Hx/BN, Ntok/BM, 3), 256>>>(ph,
            Wq + (size_t)l*Hx*Hx, Wk + (size_t)l*Hx*Hx, Wv + (size_t)l*Hx*Hx,
            bq + l*Hx, bkb + l*Hx, bv + l*Hx, pq, pk, pv);

        rope_k<<<(Ntok*NHx*32 + 255)/256, 256>>>();

        dim3 gs(Sx/BN, Sx/BM, Bx*NHx);
        gemm_k<1,0,0,1,0><<<gs,256>>>(pq, pk, nullptr, ps,
            Sx, Sx, HDx, Hx, Hx, Sx, 0.125f,
            NHx, (long long)Sx*Hx, 64, (long long)Sx*Hx, 64,
            (long long)NHx*Sx*Sx, (long long)Sx*Sx);

        softmax_k<<<dim3(Sx, Bx*NHx), 256>>>();

        dim3 gpv(1, Sx/BM, Bx*NHx);
        gemm_k<0,0,0,0,1><<<gpv,256>>>(ps, pv, nullptr, pa,
            Sx, HDx, Sx, Sx, Hx, Hx, 1.f,
            NHx, (long long)NHx*Sx*Sx, (long long)Sx*Sx,
            (long long)Sx*Hx, 64, (long long)Sx*Hx, 64);

        dim3 gp(Hx/BN, Ntok/BM, 1);
        gemm_k<0,0,1><<<gp,256>>>(pa, Wo + (size_t)l*Hx*Hx, bo + l*Hx, px,
            Ntok, Hx, Hx, Hx, Hx, Hx, 1.f, 0, 0,0,0,0,0,0);

        // ---- MoE (HMMA) ----
        ln_k<<<Ntok, 256>>>(px, ln2w + l*Hx, ln2b + l*Hx, ph);
        split_k<<<(Ntok*Hx)/256, 256>>>(ph, phh, phl, (size_t)Ntok*Hx);
        router_k<<<Ntok/8, 256>>>(ph, Wr + (size_t)l*Hx*Ex, br + l*Ex);
        zero_k<<<1, 32>>>();
        count_k<<<NSLOT/256, 256>>>();
        scan_k<<<1, 1>>>();
        scatter_k<<<NSLOT/256, 256>>>();
        moe1_hmma_k<<<dim3(Ntok/128, Fx/128, Ex), 256>>>(b1 + (size_t)l*Ex*Fx, l);
        moe2_hmma_k<<<dim3(Ntok/128, Hx/128, Ex), 256>>>(b2 + (size_t)l*Ex*Hx, l);
        combine_k<<<(Ntok*Hx + 255)/256, 256>>>();
    }

    ln_k<<<Ntok, 256>>>(px, lnfw, lnfb, ph);
    split_k<<<(Ntok*Hx)/256, 256>>>(ph, phh, phl, (size_t)Ntok*Hx);
    lmhead_hmma_k<<<dim3(Ntok/128, (Vx + 127)/128), 256>>>(out);
}

// round 13
// speedup vs baseline: 1.5901x; 1.0539x over previous
#include <cuda_runtime.h>
#include <cuda_bf16.h>
#include <math.h>
#include <stdint.h>

#define Lx   2
#define Bx   2
#define Sx   1024
#define Hx   768
#define NHx  12
#define HDx  64
#define Ex   8
#define KKx  2
#define Fx   3072
#define Vx   50257
#define Ntok (Bx*Sx)          /* 2048 */
#define NSLOT (Ntok*KKx)      /* 4096 */
#define EPSx 1e-5f

#define BM 128
#define BN 128
#define BKK 8

// ---------------- scratch (static __device__ arrays; allocation-free) -------
__device__ float g_x[Ntok*Hx];
__device__ float g_h[Ntok*Hx];
__device__ float g_q[Ntok*Hx];
__device__ float g_k[Ntok*Hx];
__device__ float g_v[Ntok*Hx];
__device__ float g_att[Ntok*Hx];
__device__ float g_scores[(size_t)Bx*NHx*Sx*Sx];   // ~100 MB
__device__ float g_oe[(size_t)NSLOT*Hx];
__device__ float g_tp[NSLOT];
__device__ int   g_ti[NSLOT];
__device__ int   g_cnt[Ex];
__device__ int   g_off[Ex+1];
__device__ int   g_fill[Ex];
__device__ int   g_slot_tok[NSLOT];
__device__ int   g_tok2slot[NSLOT];
// bf16-split operands for HMMA kernels
__device__ __nv_bfloat16 g_h_hi[Ntok*Hx];
__device__ __nv_bfloat16 g_h_lo[Ntok*Hx];
__device__ __nv_bfloat16 g_emb_hi[(size_t)Vx*Hx];
__device__ __nv_bfloat16 g_emb_lo[(size_t)Vx*Hx];
__device__ __nv_bfloat16 g_act_hi[(size_t)NSLOT*Fx];
__device__ __nv_bfloat16 g_act_lo[(size_t)NSLOT*Fx];
// transposed ([N][K]) bf16-split MoE weights
__device__ __nv_bfloat16 g_w1t_hi[(size_t)Lx*Ex*Fx*Hx];
__device__ __nv_bfloat16 g_w1t_lo[(size_t)Lx*Ex*Fx*Hx];
__device__ __nv_bfloat16 g_w2t_hi[(size_t)Lx*Ex*Hx*Fx];
__device__ __nv_bfloat16 g_w2t_lo[(size_t)Lx*Ex*Hx*Fx];

__device__ __forceinline__ float gelu_f(float x) {
    return 0.5f * x * (1.0f + erff(x * 0.70710678118654752440f));
}

__device__ __forceinline__ uint32_t smem_u32(const void* p) {
    uint32_t a;
    asm("{ .reg .u64 t; cvta.to.shared.u64 t, %1; cvt.u32.u64 %0, t; }" : "=r"(a) : "l"(p));
    return a;
}
__device__ __forceinline__ void ldmx4(uint32_t* r, uint32_t addr) {
    asm volatile("ldmatrix.sync.aligned.m8n8.x4.shared.b16 {%0,%1,%2,%3}, [%4];"
        : "=r"(r[0]), "=r"(r[1]), "=r"(r[2]), "=r"(r[3]) : "r"(addr));
}
__device__ __forceinline__ void mma16816(float* d, const uint32_t* a, uint32_t b0, uint32_t b1) {
    asm volatile("mma.sync.aligned.m16n8k16.row.col.f32.bf16.bf16.f32 "
        "{%0,%1,%2,%3}, {%4,%5,%6,%7}, {%8,%9}, {%0,%1,%2,%3};"
        : "+f"(d[0]), "+f"(d[1]), "+f"(d[2]), "+f"(d[3])
        : "r"(a[0]), "r"(a[1]), "r"(a[2]), "r"(a[3]), "r"(b0), "r"(b1));
}
__device__ __forceinline__ void cpasync16(uint32_t dst, const void* src) {
    uint64_t g = (uint64_t)__cvta_generic_to_global(src);
    asm volatile("cp.async.cg.shared.global [%0], [%1], 16;" :: "r"(dst), "l"(g) : "memory");
}
__device__ __forceinline__ void cpasync16z(uint32_t dst, const void* src, int sz) {
    uint64_t g = (uint64_t)__cvta_generic_to_global(src);
    asm volatile("cp.async.cg.shared.global [%0], [%1], 16, %2;" :: "r"(dst), "l"(g), "r"(sz) : "memory");
}
#define CP_COMMIT() asm volatile("cp.async.commit_group;" ::: "memory")
#define CP_WAIT1()  asm volatile("cp.async.wait_group 1;" ::: "memory")
#define CP_WAIT0()  asm volatile("cp.async.wait_group 0;" ::: "memory")

// ---------------- embedding gather ------------------------------------------
__global__ void embed_k(const int* __restrict__ ids, const float* __restrict__ emb)
{
    int i = blockIdx.x * 256 + threadIdx.x;
    if (i >= Ntok*Hx) return;
    int n = i / Hx, hh = i % Hx;
    g_x[i] = emb[(size_t)ids[n]*Hx + hh];
}

// ---------------- bf16 split: x = hi + lo ------------------------------------
__global__ void split_k(const float* __restrict__ X, __nv_bfloat16* __restrict__ hi,
                        __nv_bfloat16* __restrict__ lo, size_t n)
{
    size_t i = (size_t)blockIdx.x * 256 + threadIdx.x;
    if (i >= n) return;
    float v = X[i];
    __nv_bfloat16 h = __float2bfloat16_rn(v);
    hi[i] = h;
    lo[i] = __float2bfloat16_rn(v - __bfloat162float(h));
}

// ---------------- transpose + split: W[K][N] fp32 -> Wt[N][K] bf16 hi/lo ----
__global__ __launch_bounds__(256)
void tsplit_k(const float* __restrict__ W, __nv_bfloat16* __restrict__ hi,
              __nv_bfloat16* __restrict__ lo, int K, int N)
{
    __shared__ float t[32][33];
    int z = blockIdx.z;
    const float* Wb = W + (size_t)z*K*N;
    __nv_bfloat16* hb = hi + (size_t)z*N*K;
    __nv_bfloat16* lb = lo + (size_t)z*N*K;
    int tx = threadIdx.x & 31, ty = threadIdx.x >> 5;   // 32 x 8
    int k0 = blockIdx.y * 32, n0 = blockIdx.x * 32;
    #pragma unroll
    for (int r = 0; r < 4; r++)
        t[ty + r*8][tx] = Wb[(size_t)(k0 + ty + r*8)*N + n0 + tx];
    __syncthreads();
    #pragma unroll
    for (int r = 0; r < 4; r++) {
        int n = n0 + ty + r*8, k = k0 + tx;
        float v = t[tx][ty + r*8];
        __nv_bfloat16 h = __float2bfloat16_rn(v);
        hb[(size_t)n*K + k] = h;
        lb[(size_t)n*K + k] = __float2bfloat16_rn(v - __bfloat162float(h));
    }
}

// ---------------- layernorm (one block per token) ---------------------------
__global__ __launch_bounds__(256)
void ln_k(const float* __restrict__ X, const float* __restrict__ w,
          const float* __restrict__ b, float* __restrict__ Y)
{
    int n = blockIdx.x;
    __shared__ float sx[Hx];
    __shared__ float red[256];
    const float* xr = X + (size_t)n*Hx;
    int t = threadIdx.x;
    float s = 0.f;
    for (int i = t; i < Hx; i += 256) { float v = xr[i]; sx[i] = v; s += v; }
    red[t] = s; __syncthreads();
    for (int o = 128; o > 0; o >>= 1) { if (t < o) red[t] += red[t+o]; __syncthreads(); }
    float mean = red[0] * (1.0f/Hx);
    __syncthreads();
    float s2 = 0.f;
    for (int i = t; i < Hx; i += 256) { float d = sx[i]-mean; s2 += d*d; }
    __syncthreads();
    red[t] = s2; __syncthreads();
    for (int o = 128; o > 0; o >>= 1) { if (t < o) red[t] += red[t+o]; __syncthreads(); }
    float inv = rsqrtf(red[0] * (1.0f/Hx) + EPSx);
    for (int i = t; i < Hx; i += 256)
        Y[(size_t)n*Hx + i] = (sx[i]-mean)*inv*w[i] + b[i];
}

// ---------------- generic tiled SGEMM (attention + Wo) -----------------------
template<int TB, int ACT, int ADD, int CSKIP = 0, int KCLAMP = 0>
__global__ __launch_bounds__(256)
void gemm_k(const float* __restrict__ A, const float* __restrict__ B,
            const float* __restrict__ bias, float* __restrict__ C,
            int M, int N, int Kd, int lda, int ldb, int ldc, float alpha,
            int zdiv, long long sAb, long long sAh, long long sBb, long long sBh,
            long long sCb, long long sCh)
{
    const int m0 = blockIdx.y * BM;
    const int n0 = blockIdx.x * BN;
    if (CSKIP && n0 > m0) return;
    if (KCLAMP && m0 + BM < Kd) Kd = m0 + BM;
    if (zdiv > 0) {
        int z = blockIdx.z;
        int zb = z / zdiv, zh = z % zdiv;
        A += (long long)zb*sAb + (long long)zh*sAh;
        B += (long long)zb*sBb + (long long)zh*sBh;
        C += (long long)zb*sCb + (long long)zh*sCh;
    }
    __shared__ __align__(16) float As[BKK][BM];
    __shared__ __align__(16) float Bs[BKK][BN];
    const int tid = threadIdx.x;
    const int arow = tid >> 1, acol = (tid & 1) * 4;
    const int tr = (tid >> 4) << 3;
    const int tc = (tid & 15) << 3;

    float acc[8][8];
    #pragma unroll
    for (int i = 0; i < 8; i++)
        #pragma unroll
        for (int j = 0; j < 8; j++) acc[i][j] = 0.f;

    for (int k0 = 0; k0 < Kd; k0 += BKK) {
        {
            int gm = m0 + arow;
            float4 av = make_float4(0.f,0.f,0.f,0.f);
            if (gm < M) av = *(const float4*)&A[(size_t)gm*lda + k0 + acol];
            As[acol+0][arow] = av.x; As[acol+1][arow] = av.y;
            As[acol+2][arow] = av.z; As[acol+3][arow] = av.w;
        }
        if (TB) {
            int bn = tid >> 1, bk = (tid & 1) * 4;
            int gn = n0 + bn;
            float4 bv = make_float4(0.f,0.f,0.f,0.f);
            if (gn < N) bv = *(const float4*)&B[(size_t)gn*ldb + k0 + bk];
            Bs[bk+0][bn] = bv.x; Bs[bk+1][bn] = bv.y;
            Bs[bk+2][bn] = bv.z; Bs[bk+3][bn] = bv.w;
        } else {
            int bk = tid >> 5, bn = (tid & 31) * 4;
            int gn = n0 + bn;
            float4 bv = make_float4(0.f,0.f,0.f,0.f);
            if (gn < N) bv = *(const float4*)&B[(size_t)(k0+bk)*ldb + gn];
            *(float4*)&Bs[bk][bn] = bv;
        }
        __syncthreads();
        #pragma unroll
        for (int kk = 0; kk < BKK; kk++) {
            float a[8], b[8];
            #pragma unroll
            for (int i = 0; i < 8; i++) a[i] = As[kk][tr+i];
            #pragma unroll
            for (int j = 0; j < 8; j++) b[j] = Bs[kk][tc+j];
            #pragma unroll
            for (int i = 0; i < 8; i++)
                #pragma unroll
                for (int j = 0; j < 8; j++)
                    acc[i][j] = fmaf(a[i], b[j], acc[i][j]);
        }
        __syncthreads();
    }
    #pragma unroll
    for (int i = 0; i < 8; i++) {
        int gm = m0 + tr + i;
        if (gm >= M) continue;
        #pragma unroll
        for (int j = 0; j < 8; j++) {
            int gn = n0 + tc + j;
            if (gn >= N) continue;
            float v = acc[i][j] * alpha;
            if (bias) v += bias[gn];
            if (ACT == 1) v = gelu_f(v);
            size_t idx = (size_t)gm*ldc + gn;
            if (ADD) C[idx] += v; else C[idx] = v;
        }
    }
}

// ---------------- fused QKV projection (z selects q/k/v) ----------------------
__global__ __launch_bounds__(256)
void qkv_k(const float* __restrict__ Hin,
           const float* __restrict__ Wq, const float* __restrict__ Wk2, const float* __restrict__ Wv,
           const float* __restrict__ bq, const float* __restrict__ bk2, const float* __restrict__ bv,
           float* __restrict__ Q, float* __restrict__ Ko, float* __restrict__ V)
{
    int z = blockIdx.z;
    const float* B    = (z == 0) ? Wq : (z == 1) ? Wk2 : Wv;
    const float* bias = (z == 0) ? bq : (z == 1) ? bk2 : bv;
    float* C          = (z == 0) ? Q  : (z == 1) ? Ko  : V;
    const int m0 = blockIdx.y * BM;
    const int n0 = blockIdx.x * BN;
    __shared__ __align__(16) float As[BKK][BM];
    __shared__ __align__(16) float Bs[BKK][BN];
    const int tid = threadIdx.x;
    const int arow = tid >> 1, acol = (tid & 1) * 4;
    const int bk = tid >> 5, bn = (tid & 31) * 4;
    const int tr = (tid >> 4) << 3;
    const int tc = (tid & 15) << 3;

    float acc[8][8];
    #pragma unroll
    for (int i = 0; i < 8; i++)
        #pragma unroll
        for (int j = 0; j < 8; j++) acc[i][j] = 0.f;

    for (int k0 = 0; k0 < Hx; k0 += BKK) {
        float4 av = *(const float4*)&Hin[(size_t)(m0+arow)*Hx + k0 + acol];
        As[acol+0][arow] = av.x; As[acol+1][arow] = av.y;
        As[acol+2][arow] = av.z; As[acol+3][arow] = av.w;
        *(float4*)&Bs[bk][bn] = *(const float4*)&B[(size_t)(k0+bk)*Hx + n0 + bn];
        __syncthreads();
        #pragma unroll
        for (int kk = 0; kk < BKK; kk++) {
            float a[8], b[8];
            #pragma unroll
            for (int i = 0; i < 8; i++) a[i] = As[kk][tr+i];
            #pragma unroll
            for (int j = 0; j < 8; j++) b[j] = Bs[kk][tc+j];
            #pragma unroll
            for (int i = 0; i < 8; i++)
                #pragma unroll
                for (int j = 0; j < 8; j++)
                    acc[i][j] = fmaf(a[i], b[j], acc[i][j]);
        }
        __syncthreads();
    }
    #pragma unroll
    for (int i = 0; i < 8; i++)
        #pragma unroll
        for (int j = 0; j < 8; j++)
            C[(size_t)(m0+tr+i)*Hx + n0+tc+j] = acc[i][j] + bias[n0+tc+j];
}

// ---------------- bf16-split HMMA GEMM cores --------------------------------
#define LM_LDS 40                     /* 32 + 8 pad; conflict-free for ldmatrix */
#define LM_TILE (128*LM_LDS)          /* bf16 elems per tile */
#define LM_DSMEM (2*4*LM_TILE*2)      /* 2 buffers x 4 tiles x bytes = 81920 */

// C[2048, 50257] = h @ emb^T — cp.async double-buffered
__global__ __launch_bounds__(256)
void lmhead_hmma_k(float* __restrict__ C)
{
    extern __shared__ __nv_bfloat16 dsm[];
    const int tid = threadIdx.x;
    const int wid = tid >> 5, lane = tid & 31;
    const int m0 = blockIdx.x * 128;
    const int n0 = blockIdx.y * 128;
    const int wm = (wid & 3) * 32;
    const int wn = (wid >> 2) * 64;

    float acc[2][8][4];
    #pragma unroll
    for (int mt = 0; mt < 2; mt++)
        #pragma unroll
        for (int nt = 0; nt < 8; nt++)
            #pragma unroll
            for (int r = 0; r < 4; r++) acc[mt][nt][r] = 0.f;

    const int lrow = tid >> 1;
    const int lcol = (tid & 1) * 16;
    const int a_r = lane & 15, a_c = (lane >> 4) * 8;
    const int b_r = (lane & 7) + ((lane >> 4) & 1) * 8;
    const int b_c = ((lane >> 3) & 1) * 8;

    const size_t arow_off = (size_t)(m0 + lrow)*Hx;
    const int nB = n0 + lrow;
    const size_t brow_off = (size_t)((nB < Vx) ? nB : (Vx - 1))*Hx;
    const int bsz = (nB < Vx) ? 16 : 0;
    const uint32_t sdst = smem_u32(dsm) + (uint32_t)(lrow*LM_LDS + lcol)*2u;

    auto issue = [&](int kc, int b) {
        const int kg = kc*32 + lcol;
        uint32_t d = sdst + (uint32_t)(b*4*LM_TILE)*2u;
        cpasync16 (d,                        &g_h_hi[arow_off + kg]);
        cpasync16 (d + 16,                   &g_h_hi[arow_off + kg + 8]);
        cpasync16 (d + LM_TILE*2,            &g_h_lo[arow_off + kg]);
        cpasync16 (d + LM_TILE*2 + 16,       &g_h_lo[arow_off + kg + 8]);
        cpasync16z(d + 2*LM_TILE*2,          &g_emb_hi[brow_off + kg],     bsz);
        cpasync16z(d + 2*LM_TILE*2 + 16,     &g_emb_hi[brow_off + kg + 8], bsz);
        cpasync16z(d + 3*LM_TILE*2,          &g_emb_lo[brow_off + kg],     bsz);
        cpasync16z(d + 3*LM_TILE*2 + 16,     &g_emb_lo[brow_off + kg + 8], bsz);
    };

    issue(0, 0);
    CP_COMMIT();

    for (int kc = 0; kc < Hx/32; kc++) {
        if (kc + 1 < Hx/32) {
            issue(kc + 1, (kc + 1) & 1);
            CP_COMMIT();
            CP_WAIT1();
        } else {
            CP_WAIT0();
        }
        __syncthreads();
        const __nv_bfloat16* buf = dsm + (kc & 1)*4*LM_TILE;
        #pragma unroll
        for (int pass = 0; pass < 3; pass++) {
            const __nv_bfloat16* pA = buf + ((pass == 2) ? 1 : 0)*LM_TILE;
            const __nv_bfloat16* pB = buf + ((pass == 1) ? 3 : 2)*LM_TILE;
            #pragma unroll
            for (int ks = 0; ks < 2; ks++) {
                const int k0 = ks * 16;
                uint32_t af[2][4];
                #pragma unroll
                for (int mt = 0; mt < 2; mt++)
                    ldmx4(af[mt], smem_u32(pA + (wm + mt*16 + a_r)*LM_LDS + k0 + a_c));
                uint32_t bf[4][4];
                #pragma unroll
                for (int bq = 0; bq < 4; bq++)
                    ldmx4(bf[bq], smem_u32(pB + (wn + bq*16 + b_r)*LM_LDS + k0 + b_c));
                #pragma unroll
                for (int mt = 0; mt < 2; mt++)
                    #pragma unroll
                    for (int nt = 0; nt < 8; nt++)
                        mma16816(acc[mt][nt], af[mt],
                                 bf[nt >> 1][(nt & 1)*2], bf[nt >> 1][(nt & 1)*2 + 1]);
            }
        }
        __syncthreads();
    }

    const int er = lane >> 2, ec = (lane & 3) * 2;
    #pragma unroll
    for (int mt = 0; mt < 2; mt++) {
        #pragma unroll
        for (int nt = 0; nt < 8; nt++) {
            int row = m0 + wm + mt*16 + er;
            int col = n0 + wn + nt*8 + ec;
            if (col < Vx) {
                C[(size_t)row*Vx + col] = acc[mt][nt][0];
                C[(size_t)(row+8)*Vx + col] = acc[mt][nt][2];
            }
            if (col + 1 < Vx) {
                C[(size_t)row*Vx + col + 1] = acc[mt][nt][1];
                C[(size_t)(row+8)*Vx + col + 1] = acc[mt][nt][3];
            }
        }
    }
}

// MoE stage 1: act = gelu(gather(h) @ W1t^T + b1); writes bf16 hi/lo
__global__ __launch_bounds__(256)
void moe1_hmma_k(const float* __restrict__ b1l, int layer)
{
    __shared__ __nv_bfloat16 sAhi[128][LM_LDS], sAlo[128][LM_LDS];
    __shared__ __nv_bfloat16 sBhi[128][LM_LDS], sBlo[128][LM_LDS];
    const int e = blockIdx.z;
    const int base = g_off[e];
    const int cnt  = g_off[e+1] - base;
    const int m0 = blockIdx.x * 128;
    if (m0 >= cnt) return;
    const int n0 = blockIdx.y * 128;
    const size_t wb = ((size_t)layer*Ex + e)*(size_t)Fx*Hx;
    const float* bias = b1l + (size_t)e*Fx;

    const int tid = threadIdx.x;
    const int wid = tid >> 5, lane = tid & 31;
    const int wm = (wid & 3) * 32;
    const int wn = (wid >> 2) * 64;

    float acc[2][8][4];
    #pragma unroll
    for (int mt = 0; mt < 2; mt++)
        #pragma unroll
        for (int nt = 0; nt < 8; nt++)
            #pragma unroll
            for (int r = 0; r < 4; r++) acc[mt][nt][r] = 0.f;

    const int lrow = tid >> 1;
    const int lcol = (tid & 1) * 16;
    const int a_r = lane & 15, a_c = (lane >> 4) * 8;
    const int b_r = (lane & 7) + ((lane >> 4) & 1) * 8;
    const int b_c = ((lane >> 3) & 1) * 8;

    int tok = (m0 + lrow < cnt) ? g_slot_tok[base + m0 + lrow] : -1;

    for (int kc = 0; kc < Hx/32; kc++) {
        const int kg = kc * 32 + lcol;
        {
            uint4 h0 = make_uint4(0,0,0,0), l0 = h0;
            uint4 h1 = h0, l1 = h0;
            if (tok >= 0) {
                const uint4* s = (const uint4*)&g_h_hi[(size_t)tok*Hx + kg];
                h0 = s[0]; h1 = s[1];
                s = (const uint4*)&g_h_lo[(size_t)tok*Hx + kg];
                l0 = s[0]; l1 = s[1];
            }
            *(uint4*)&sAhi[lrow][lcol]   = h0;
            *(uint4*)&sAhi[lrow][lcol+8] = h1;
            *(uint4*)&sAlo[lrow][lcol]   = l0;
            *(uint4*)&sAlo[lrow][lcol+8] = l1;
        }
        {
            size_t gidx = wb + (size_t)(n0 + lrow)*Hx + kg;
            const uint4* s = (const uint4*)&g_w1t_hi[gidx];
            *(uint4*)&sBhi[lrow][lcol]   = s[0];
            *(uint4*)&sBhi[lrow][lcol+8] = s[1];
            s = (const uint4*)&g_w1t_lo[gidx];
            *(uint4*)&sBlo[lrow][lcol]   = s[0];
            *(uint4*)&sBlo[lrow][lcol+8] = s[1];
        }
        __syncthreads();
        #pragma unroll
        for (int pass = 0; pass < 3; pass++) {
            const __nv_bfloat16 (*pA)[LM_LDS] = (pass == 2) ? sAlo : sAhi;
            const __nv_bfloat16 (*pB)[LM_LDS] = (pass == 1) ? sBlo : sBhi;
            #pragma unroll
            for (int ks = 0; ks < 2; ks++) {
                const int k0 = ks * 16;
                uint32_t af[2][4];
                #pragma unroll
                for (int mt = 0; mt < 2; mt++)
                    ldmx4(af[mt], smem_u32(&pA[wm + mt*16 + a_r][k0 + a_c]));
                uint32_t bf[4][4];
                #pragma unroll
                for (int bq = 0; bq < 4; bq++)
                    ldmx4(bf[bq], smem_u32(&pB[wn + bq*16 + b_r][k0 + b_c]));
                #pragma unroll
                for (int mt = 0; mt < 2; mt++)
                    #pragma unroll
                    for (int nt = 0; nt < 8; nt++)
                        mma16816(acc[mt][nt], af[mt],
                                 bf[nt >> 1][(nt & 1)*2], bf[nt >> 1][(nt & 1)*2 + 1]);
            }
        }
        __syncthreads();
    }

    const int er = lane >> 2, ec = (lane & 3) * 2;
    #pragma unroll
    for (int mt = 0; mt < 2; mt++) {
        #pragma unroll
        for (int nt = 0; nt < 8; nt++) {
            int rl = wm + mt*16 + er;
            int col = n0 + wn + nt*8 + ec;
            #pragma unroll
            for (int rr = 0; rr < 2; rr++) {
                int row = m0 + rl + rr*8;
                if (row >= cnt) continue;
                #pragma unroll
                for (int cc = 0; cc < 2; cc++) {
                    float g = gelu_f(acc[mt][nt][rr*2 + cc] + bias[col + cc]);
                    __nv_bfloat16 h = __float2bfloat16_rn(g);
                    size_t idx = (size_t)(base + row)*Fx + col + cc;
                    g_act_hi[idx] = h;
                    g_act_lo[idx] = __float2bfloat16_rn(g - __bfloat162float(h));
                }
            }
        }
    }
}

// MoE stage 2: oe = act @ W2t^T + b2 (fp32 out)
__global__ __launch_bounds__(256)
void moe2_hmma_k(const float* __restrict__ b2l, int layer)
{
    __shared__ __nv_bfloat16 sAhi[128][LM_LDS], sAlo[128][LM_LDS];
    __shared__ __nv_bfloat16 sBhi[128][LM_LDS], sBlo[128][LM_LDS];
    const int e = blockIdx.z;
    const int base = g_off[e];
    const int cnt  = g_off[e+1] - base;
    const int m0 = blockIdx.x * 128;
    if (m0 >= cnt) return;
    const int n0 = blockIdx.y * 128;
    const size_t wb = ((size_t)layer*Ex + e)*(size_t)Fx*Hx;
    const float* bias = b2l + (size_t)e*Hx;

    const int tid = threadIdx.x;
    const int wid = tid >> 5, lane = tid & 31;
    const int wm = (wid & 3) * 32;
    const int wn = (wid >> 2) * 64;

    float acc[2][8][4];
    #pragma unroll
    for (int mt = 0; mt < 2; mt++)
        #pragma unroll
        for (int nt = 0; nt < 8; nt++)
            #pragma unroll
            for (int r = 0; r < 4; r++) acc[mt][nt][r] = 0.f;

    const int lrow = tid >> 1;
    const int lcol = (tid & 1) * 16;
    const int a_r = lane & 15, a_c = (lane >> 4) * 8;
    const int b_r = (lane & 7) + ((lane >> 4) & 1) * 8;
    const int b_c = ((lane >> 3) & 1) * 8;

    const bool arow_ok = (m0 + lrow < cnt);
    const size_t aslot = (size_t)(base + m0 + lrow)*Fx;

    for (int kc = 0; kc < Fx/32; kc++) {
        const int kg = kc * 32 + lcol;
        {
            uint4 h0 = make_uint4(0,0,0,0), h1 = h0, l0 = h0, l1 = h0;
            if (arow_ok) {
                const uint4* s = (const uint4*)&g_act_hi[aslot + kg];
                h0 = s[0]; h1 = s[1];
                s = (const uint4*)&g_act_lo[aslot + kg];
                l0 = s[0]; l1 = s[1];
            }
            *(uint4*)&sAhi[lrow][lcol]   = h0;
            *(uint4*)&sAhi[lrow][lcol+8] = h1;
            *(uint4*)&sAlo[lrow][lcol]   = l0;
            *(uint4*)&sAlo[lrow][lcol+8] = l1;
        }
        {
            size_t gidx = wb + (size_t)(n0 + lrow)*Fx + kg;
            const uint4* s = (const uint4*)&g_w2t_hi[gidx];
            *(uint4*)&sBhi[lrow][lcol]   = s[0];
            *(uint4*)&sBhi[lrow][lcol+8] = s[1];
            s = (const uint4*)&g_w2t_lo[gidx];
            *(uint4*)&sBlo[lrow][lcol]   = s[0];
            *(uint4*)&sBlo[lrow][lcol+8] = s[1];
        }
        __syncthreads();
        #pragma unroll
        for (int pass = 0; pass < 3; pass++) {
            const __nv_bfloat16 (*pA)[LM_LDS] = (pass == 2) ? sAlo : sAhi;
            const __nv_bfloat16 (*pB)[LM_LDS] = (pass == 1) ? sBlo : sBhi;
            #pragma unroll
            for (int ks = 0; ks < 2; ks++) {
                const int k0 = ks * 16;
                uint32_t af[2][4];
                #pragma unroll
                for (int mt = 0; mt < 2; mt++)
                    ldmx4(af[mt], smem_u32(&pA[wm + mt*16 + a_r][k0 + a_c]));
                uint32_t bf[4][4];
                #pragma unroll
                for (int bq = 0; bq < 4; bq++)
                    ldmx4(bf[bq], smem_u32(&pB[wn + bq*16 + b_r][k0 + b_c]));
                #pragma unroll
                for (int mt = 0; mt < 2; mt++)
                    #pragma unroll
                    for (int nt = 0; nt < 8; nt++)
                        mma16816(acc[mt][nt], af[mt],
                                 bf[nt >> 1][(nt & 1)*2], bf[nt >> 1][(nt & 1)*2 + 1]);
            }
        }
        __syncthreads();
    }

    const int er = lane >> 2, ec = (lane & 3) * 2;
    #pragma unroll
    for (int mt = 0; mt < 2; mt++) {
        #pragma unroll
        for (int nt = 0; nt < 8; nt++) {
            int rl = wm + mt*16 + er;
            int col = n0 + wn + nt*8 + ec;
            #pragma unroll
            for (int rr = 0; rr < 2; rr++) {
                int row = m0 + rl + rr*8;
                if (row >= cnt) continue;
                #pragma unroll
                for (int cc = 0; cc < 2; cc++)
                    g_oe[(size_t)(base + row)*Hx + col + cc] =
                        acc[mt][nt][rr*2 + cc] + bias[col + cc];
            }
        }
    }
}

// ---------------- RoPE -------------------------------------------------------
__global__ void rope_k()
{
    int i = blockIdx.x * 256 + threadIdx.x;
    if (i >= Ntok*NHx*32) return;
    int d = i & 31;
    int rest = i >> 5;
    int head = rest % NHx;
    int n = rest / NHx;
    int s = n & (Sx-1);
    double inv = exp(-9.210340371976184 * (double)d / 32.0);
    double ang = (double)s * inv;
    float c = (float)cos(ang);
    float sn = (float)sin(ang);
    size_t base = (size_t)n*Hx + head*64 + d;
    float a = g_q[base], b2 = g_q[base+32];
    g_q[base]    = a*c - b2*sn;
    g_q[base+32] = b2*c + a*sn;
    a = g_k[base]; b2 = g_k[base+32];
    g_k[base]    = a*c - b2*sn;
    g_k[base+32] = b2*c + a*sn;
}

// ---------------- causal-masked softmax --------------------------------------
__global__ __launch_bounds__(256)
void softmax_k()
{
    int qi = blockIdx.x;
    int z  = blockIdx.y;
    float* row = g_scores + (size_t)z*Sx*Sx + (size_t)qi*Sx;
    __shared__ float red[256];
    int t = threadIdx.x;
    float lv[4];
    float mx = -3.0e38f;
    #pragma unroll
    for (int u = 0; u < 4; u++) {
        int j = t + u*256;
        float v = (j > qi) ? -INFINITY : row[j];
        lv[u] = v; mx = fmaxf(mx, v);
    }
    red[t] = mx; __syncthreads();
    for (int o = 128; o > 0; o >>= 1) { if (t < o) red[t] = fmaxf(red[t], red[t+o]); __syncthreads(); }
    mx = red[0]; __syncthreads();
    float sum = 0.f;
    #pragma unroll
    for (int u = 0; u < 4; u++) { lv[u] = expf(lv[u]-mx); sum += lv[u]; }
    red[t] = sum; __syncthreads();
    for (int o = 128; o > 0; o >>= 1) { if (t < o) red[t] += red[t+o]; __syncthreads(); }
    float inv = 1.0f / red[0];
    #pragma unroll
    for (int u = 0; u < 4; u++) row[t + u*256] = lv[u]*inv;
}

// ---------------- MoE router -------------------------------------------------
__global__ void router_k(const float* __restrict__ Hin, const float* __restrict__ Wr,
                         const float* __restrict__ br)
{
    int warp = threadIdx.x >> 5, lane = threadIdx.x & 31;
    int n = blockIdx.x * 8 + warp;
    if (n >= Ntok) return;
    const float* hr = Hin + (size_t)n*Hx;
    float p[Ex];
    #pragma unroll
    for (int e = 0; e < Ex; e++) {
        float s = 0.f;
        for (int i = lane; i < Hx; i += 32) s = fmaf(hr[i], Wr[i*Ex + e], s);
        #pragma unroll
        for (int o = 16; o > 0; o >>= 1) s += __shfl_xor_sync(0xffffffffu, s, o);
        p[e] = s + br[e];
    }
    if (lane == 0) {
        float m = p[0];
        #pragma unroll
        for (int e = 1; e < Ex; e++) m = fmaxf(m, p[e]);
        float sum = 0.f;
        #pragma unroll
        for (int e = 0; e < Ex; e++) { p[e] = expf(p[e]-m); sum += p[e]; }
        float is = 1.0f/sum;
        #pragma unroll
        for (int e = 0; e < Ex; e++) p[e] *= is;
        int i1 = 0;
        #pragma unroll
        for (int e = 1; e < Ex; e++) if (p[e] > p[i1]) i1 = e;
        int i2 = (i1 == 0) ? 1 : 0;
        #pragma unroll
        for (int e = 0; e < Ex; e++) { if (e == i1 || e == i2) continue; if (p[e] > p[i2]) i2 = e; }
        float t1 = p[i1], t2 = p[i2];
        float isum = 1.0f / (t1 + t2 + 1e-9f);
        g_ti[n*2] = i1;  g_ti[n*2+1] = i2;
        g_tp[n*2] = t1*isum; g_tp[n*2+1] = t2*isum;
    }
}

__global__ void zero_k() { int t = threadIdx.x; if (t < Ex) { g_cnt[t] = 0; g_fill[t] = 0; } }
__global__ void count_k() { int i = blockIdx.x*256+threadIdx.x; if (i < NSLOT) atomicAdd(&g_cnt[g_ti[i]], 1); }
__global__ void scan_k()  { g_off[0] = 0; for (int e = 0; e < Ex; e++) g_off[e+1] = g_off[e] + g_cnt[e]; }
__global__ void scatter_k()
{
    int i = blockIdx.x*256+threadIdx.x;
    if (i >= NSLOT) return;
    int e = g_ti[i];
    int pos = atomicAdd(&g_fill[e], 1);
    int slot = g_off[e] + pos;
    g_slot_tok[slot] = i >> 1;
    g_tok2slot[i] = slot;
}

// ---------------- combine ----------------------------------------------------
__global__ void combine_k()
{
    int i = blockIdx.x*256+threadIdx.x;
    if (i >= Ntok*Hx) return;
    int n = i / Hx, hh = i % Hx;
    int s0 = g_tok2slot[n*2], s1 = g_tok2slot[n*2+1];
    g_x[i] += g_tp[n*2]  * g_oe[(size_t)s0*Hx + hh]
            + g_tp[n*2+1]* g_oe[(size_t)s1*Hx + hh];
}

// ---------------- host orchestration ----------------------------------------
extern "C" void kernel_launch(void* const* d_in, const int* in_sizes, int n_in,
                              void* d_out, int out_size)
{
    const int*   ids  = (const int*)  d_in[0];
    const float* emb  = (const float*)d_in[1];
    const float* ln1w = (const float*)d_in[2];
    const float* ln1b = (const float*)d_in[3];
    const float* ln2w = (const float*)d_in[4];
    const float* ln2b = (const float*)d_in[5];
    const float* lnfw = (const float*)d_in[6];
    const float* lnfb = (const float*)d_in[7];
    const float* Wq   = (const float*)d_in[8];
    const float* bq   = (const float*)d_in[9];
    const float* Wk   = (const float*)d_in[10];
    const float* bkb  = (const float*)d_in[11];
    const float* Wv   = (const float*)d_in[12];
    const float* bv   = (const float*)d_in[13];
    const float* Wo   = (const float*)d_in[14];
    const float* bo   = (const float*)d_in[15];
    const float* Wr   = (const float*)d_in[16];
    const float* br   = (const float*)d_in[17];
    const float* W1   = (const float*)d_in[18];
    const float* b1   = (const float*)d_in[19];
    const float* W2   = (const float*)d_in[20];
    const float* b2   = (const float*)d_in[21];
    float* out = (float*)d_out;

    float *px, *ph, *pq, *pk, *pv, *pa, *ps;
    cudaGetSymbolAddress((void**)&px, g_x);
    cudaGetSymbolAddress((void**)&ph, g_h);
    cudaGetSymbolAddress((void**)&pq, g_q);
    cudaGetSymbolAddress((void**)&pk, g_k);
    cudaGetSymbolAddress((void**)&pv, g_v);
    cudaGetSymbolAddress((void**)&pa, g_att);
    cudaGetSymbolAddress((void**)&ps, g_scores);
    __nv_bfloat16 *phh, *phl, *peh, *pel, *pw1h, *pw1l, *pw2h, *pw2l;
    cudaGetSymbolAddress((void**)&phh, g_h_hi);
    cudaGetSymbolAddress((void**)&phl, g_h_lo);
    cudaGetSymbolAddress((void**)&peh, g_emb_hi);
    cudaGetSymbolAddress((void**)&pel, g_emb_lo);
    cudaGetSymbolAddress((void**)&pw1h, g_w1t_hi);
    cudaGetSymbolAddress((void**)&pw1l, g_w1t_lo);
    cudaGetSymbolAddress((void**)&pw2h, g_w2t_hi);
    cudaGetSymbolAddress((void**)&pw2l, g_w2t_lo);

    cudaFuncSetAttribute(lmhead_hmma_k, cudaFuncAttributeMaxDynamicSharedMemorySize, LM_DSMEM);

    embed_k<<<(Ntok*Hx + 255)/256, 256>>>(ids, emb);
    split_k<<<(int)(((size_t)Vx*Hx + 255)/256), 256>>>(emb, peh, pel, (size_t)Vx*Hx);
    // transpose-split MoE weights: W[K][N] -> Wt[N][K] bf16 hi/lo
    tsplit_k<<<dim3(Fx/32, Hx/32, Lx*Ex), 256>>>(W1, pw1h, pw1l, Hx, Fx);
    tsplit_k<<<dim3(Hx/32, Fx/32, Lx*Ex), 256>>>(W2, pw2h, pw2l, Fx, Hx);

    for (int l = 0; l < Lx; l++) {
        ln_k<<<Ntok, 256>>>(px, ln1w + l*Hx, ln1b + l*Hx, ph);

        qkv_k<<<dim3(Hx/BN, Ntok/BM, 3), 256>>>(ph,
            Wq + (size_t)l*Hx*Hx, Wk + (size_t)l*Hx*Hx, Wv + (size_t)l*Hx*Hx,
            bq + l*Hx, bkb + l*Hx, bv + l*Hx, pq, pk, pv);

        rope_k<<<(Ntok*NHx*32 + 255)/256, 256>>>();

        dim3 gs(Sx/BN, Sx/BM, Bx*NHx);
        gemm_k<1,0,0,1,0><<<gs,256>>>(pq, pk, nullptr, ps,
            Sx, Sx, HDx, Hx, Hx, Sx, 0.125f,
            NHx, (long long)Sx*Hx, 64, (long long)Sx*Hx, 64,
            (long long)NHx*Sx*Sx, (long long)Sx*Sx);

        softmax_k<<<dim3(Sx, Bx*NHx), 256>>>();

        dim3 gpv(1, Sx/BM, Bx*NHx);
        gemm_k<0,0,0,0,1><<<gpv,256>>>(ps, pv, nullptr, pa,
            Sx, HDx, Sx, Sx, Hx, Hx, 1.f,
            NHx, (long long)NHx*Sx*Sx, (long long)Sx*Sx,
            (long long)Sx*Hx, 64, (long long)Sx*Hx, 64);

        dim3 gp(Hx/BN, Ntok/BM, 1);
        gemm_k<0,0,1><<<gp,256>>>(pa, Wo + (size_t)l*Hx*Hx, bo + l*Hx, px,
            Ntok, Hx, Hx, Hx, Hx, Hx, 1.f, 0, 0,0,0,0,0,0);

        // ---- MoE (HMMA) ----
        ln_k<<<Ntok, 256>>>(px, ln2w + l*Hx, ln2b + l*Hx, ph);
        split_k<<<(Ntok*Hx)/256, 256>>>(ph, phh, phl, (size_t)Ntok*Hx);
        router_k<<<Ntok/8, 256>>>(ph, Wr + (size_t)l*Hx*Ex, br + l*Ex);
        zero_k<<<1, 32>>>();
        count_k<<<NSLOT/256, 256>>>();
        scan_k<<<1, 1>>>();
        scatter_k<<<NSLOT/256, 256>>>();
        moe1_hmma_k<<<dim3(Ntok/128, Fx/128, Ex), 256>>>(b1 + (size_t)l*Ex*Fx, l);
        moe2_hmma_k<<<dim3(Ntok/128, Hx/128, Ex), 256>>>(b2 + (size_t)l*Ex*Hx, l);
        combine_k<<<(Ntok*Hx + 255)/256, 256>>>();
    }

    ln_k<<<Ntok, 256>>>(px, lnfw, lnfb, ph);
    split_k<<<(Ntok*Hx)/256, 256>>>(ph, phh, phl, (size_t)Ntok*Hx);
    lmhead_hmma_k<<<dim3(Ntok/128, (Vx + 127)/128), 256, LM_DSMEM>>>(out);
}